// round 7
// baseline (speedup 1.0000x reference)
#include <cuda_runtime.h>
#include <cstddef>

#define BATCH 32
#define DCH 256
#define NG 64
#define PPAD 1088   // padded total conv positions (17 * 64)

__constant__ int c_off[31] = {0,64,128,192,252,312,372,432,488,544,600,656,708,760,812,
                              864,888,912,936,960,980,1000,1020,
                              1040,1048,1056,1064,1072,1076,1080,1084};

// ---------------- scratch ----------------
__device__ float g_wT2[29 * 512 * 256];
__device__ float g_wT3[2 * 768 * 256];
__device__ float g_wP[256 * 768];
__device__ float g_cur[(size_t)BATCH * DCH * PPAD];
__device__ float g_Pc[(size_t)BATCH * PPAD * DCH];
__device__ float g_P[(size_t)BATCH * NG * 768];

// ---------------- f32x2 helpers ----------------
__device__ __forceinline__ void fma2(unsigned long long& d, unsigned long long a,
                                     unsigned long long b) {
    asm("fma.rn.f32x2 %0, %1, %2, %3;" : "=l"(d) : "l"(a), "l"(b), "l"(d));
}
__device__ __forceinline__ unsigned long long dup2(float x) {
    unsigned long long r;
    unsigned int xi = __float_as_uint(x);
    asm("mov.b64 %0, {%1, %1};" : "=l"(r) : "r"(xi));
    return r;
}
__device__ __forceinline__ void cluster_sync_all() {
    asm volatile("barrier.cluster.arrive.aligned;" ::: "memory");
    asm volatile("barrier.cluster.wait.aligned;" ::: "memory");
}

// ---------------- generalized transpose ----------------
__global__ void trans_k(const float* __restrict__ in, float* __restrict__ out,
                        int R, int C, int in_ld, int out_ld,
                        size_t in_bs, size_t out_bs) {
    __shared__ float tile[32][33];
    int bat = blockIdx.z;
    int c0 = blockIdx.x * 32, r0 = blockIdx.y * 32;
    const float* ib = in + (size_t)bat * in_bs;
    float* ob = out + (size_t)bat * out_bs;
    int tx = threadIdx.x, ty = threadIdx.y;
#pragma unroll
    for (int s = 0; s < 32; s += 8) {
        int r = r0 + ty + s, c = c0 + tx;
        if (r < R && c < C) tile[ty + s][tx] = ib[(size_t)r * in_ld + c];
    }
    __syncthreads();
#pragma unroll
    for (int s = 0; s < 32; s += 8) {
        int c = c0 + ty + s, r = r0 + tx;
        if (c < C && r < R) ob[(size_t)c * out_ld + r] = tile[tx][ty + s];
    }
}

// ---------------- per-layer GEMM body: TM x 32 tile, 2-wg split-K ----------------
// out[b, n, out_off+m] = bias[n] + sum_{c,kk} in[b, c, in_off+m*cs+kk]*wT[(c*KSZ+kk)*256+n]
// 256 threads = 2 warpgroups split K; per-thread fragment MR(M) x 4(N); MR = TM/16.
template <int KSZ, int TM>
__device__ __forceinline__ void gemm_layer(
    const float* __restrict__ in, int in_row_len, int in_off, int cstride,
    const float* __restrict__ wT, const float* __restrict__ bias,
    float* __restrict__ outp, int out_off, int M_total,
    int b, int nblk, float* smem) {
    constexpr int KTOT = KSZ * 256;
    constexpr int KH = KTOT / 2;
    constexpr int KC = (KSZ == 3) ? 24 : 32;
    constexpr int NCH = KH / KC;
    constexpr int AG = 128 / TM;
    constexpr int NA = KC / AG;     // A floats per thread per chunk
    constexpr int NB = KC / 8;      // B float2 per thread per chunk
    constexpr int MR = TM / 16;
    constexpr int WGS = 2 * KC * TM + 2 * KC * 32;

    int tid = threadIdx.x;
    int wg = tid >> 7;
    int wtid = tid & 127;
    float* As = smem + wg * WGS;
    float* Bs = As + 2 * KC * TM;
    float* Red = smem;  // aliased after compute: [TM][32]

    int m0 = (wtid & 15) * MR;
    int n0 = (wtid >> 4) * 4;
    int am = wtid % TM;
    int ak0 = wtid / TM;
    int brow = wtid >> 4;          // 0..7
    int bcol = (wtid & 15) * 2;

    const float* inb = in + (size_t)b * DCH * in_row_len + in_off;
    int kbase = wg * KH;

    float aA[NA];
    float2 bB[NB];
    auto gload = [&](int ch) {
        int c0k = kbase + ch * KC;
#pragma unroll
        for (int i = 0; i < NA; i++) {
            int k = c0k + ak0 + AG * i;
            int c = k / KSZ;
            int kk = k - c * KSZ;
            aA[i] = (am < M_total)
                        ? inb[(size_t)c * in_row_len + am * cstride + kk]
                        : 0.f;
        }
#pragma unroll
        for (int i = 0; i < NB; i++) {
            int k = c0k + brow + 8 * i;
            bB[i] = *(const float2*)&wT[(size_t)k * 256 + nblk + bcol];
        }
    };
    auto sts = [&](int buf) {
#pragma unroll
        for (int i = 0; i < NA; i++)
            As[buf * KC * TM + (ak0 + AG * i) * TM + am] = aA[i];
#pragma unroll
        for (int i = 0; i < NB; i++)
            *(float2*)&Bs[buf * KC * 32 + (brow + 8 * i) * 32 + bcol] = bB[i];
    };

    unsigned long long acc[MR][2];
#pragma unroll
    for (int mi = 0; mi < MR; mi++) {
        acc[mi][0] = 0ULL;
        acc[mi][1] = 0ULL;
    }

    gload(0);
    sts(0);
    __syncthreads();

#pragma unroll 1
    for (int ch = 0; ch < NCH; ch++) {
        int buf = ch & 1;
        if (ch + 1 < NCH) gload(ch + 1);
#pragma unroll
        for (int k = 0; k < KC; k++) {
            float a[MR];
            const float* ap = &As[buf * KC * TM + k * TM + m0];
            if (MR == 4) {
                float4 v = *(const float4*)ap;
                a[0] = v.x; a[1] = v.y; a[2] = v.z; a[3] = v.w;
            } else if (MR == 2) {
                float2 v = *(const float2*)ap;
                a[0] = v.x; a[1] = v.y;
            } else {
                a[0] = *ap;
            }
            ulonglong2 bv = *(const ulonglong2*)&Bs[buf * KC * 32 + k * 32 + n0];
#pragma unroll
            for (int mi = 0; mi < MR; mi++) {
                unsigned long long ad = dup2(a[mi]);
                fma2(acc[mi][0], ad, bv.x);
                fma2(acc[mi][1], ad, bv.y);
            }
        }
        if (ch + 1 < NCH) {
            sts(buf ^ 1);
            __syncthreads();
        }
    }

    float res[MR][4];
#pragma unroll
    for (int mi = 0; mi < MR; mi++)
#pragma unroll
        for (int p = 0; p < 2; p++) {
            union { unsigned long long u; float2 f; } cv;
            cv.u = acc[mi][p];
            res[mi][2 * p] = cv.f.x;
            res[mi][2 * p + 1] = cv.f.y;
        }

    __syncthreads();
    if (wg == 1) {
#pragma unroll
        for (int mi = 0; mi < MR; mi++)
            *(float4*)&Red[(m0 + mi) * 32 + n0] =
                make_float4(res[mi][0], res[mi][1], res[mi][2], res[mi][3]);
    }
    __syncthreads();

    if (wg == 0) {
#pragma unroll
        for (int mi = 0; mi < MR; mi++) {
            const float* rp = &Red[(m0 + mi) * 32 + n0];
#pragma unroll
            for (int j = 0; j < 4; j++) res[mi][j] += rp[j];
        }
#pragma unroll
        for (int j = 0; j < 4; j++) {
            int n = nblk + n0 + j;
            float bv = __ldg(bias + n);
            float* orow = outp + ((size_t)b * DCH + n) * PPAD + out_off + m0;
            if (m0 + MR <= M_total) {
                if (MR == 4) {
                    *(float4*)orow = make_float4(res[0][j] + bv, res[1][j] + bv,
                                                 res[2][j] + bv, res[3][j] + bv);
                } else if (MR == 2) {
                    *(float2*)orow = make_float2(res[0][j] + bv, res[1][j] + bv);
                } else {
                    orow[0] = res[0][j] + bv;
                }
            } else {
#pragma unroll
                for (int mi = 0; mi < MR; mi++)
                    if (m0 + mi < M_total) orow[mi] = res[mi][j] + bv;
            }
        }
    }
    __syncthreads();
}

// ---------------- fused 31-layer chain: 8-CTA clusters (one batch each) ----------------
__global__ void __launch_bounds__(256, 2) __cluster_dims__(8, 1, 1)
chain_fused(const float* __restrict__ x,
            const float* __restrict__ wT2, const float* __restrict__ b2,
            const float* __restrict__ wT3, const float* __restrict__ b3,
            float* __restrict__ cur) {
    extern __shared__ float smem[];
    int b = blockIdx.x >> 3;
    int nblk = (blockIdx.x & 7) * 32;

    int i2 = 0;
#pragma unroll 1
    for (int l = 0; l < 15; l++) {
        const float* in = (l == 0) ? x : cur;
        int irl = (l == 0) ? NG : PPAD;
        int ioff = (l == 0) ? 0 : c_off[l - 1];
        gemm_layer<2, 64>(in, irl, ioff, 1, wT2 + (size_t)i2 * 512 * 256,
                          b2 + i2 * 256, cur, c_off[l], 63 - l, b, nblk, smem);
        i2++;
        cluster_sync_all();
    }
    gemm_layer<3, 32>(cur, PPAD, c_off[14], 2, wT3, b3, cur, c_off[15], 24, b, nblk,
                      smem);
    cluster_sync_all();
#pragma unroll 1
    for (int l = 16; l < 23; l++) {
        gemm_layer<2, 32>(cur, PPAD, c_off[l - 1], 1, wT2 + (size_t)i2 * 512 * 256,
                          b2 + i2 * 256, cur, c_off[l], 39 - l, b, nblk, smem);
        i2++;
        cluster_sync_all();
    }
    gemm_layer<3, 16>(cur, PPAD, c_off[22], 2, wT3 + (size_t)768 * 256, b3 + 256, cur,
                      c_off[23], 8, b, nblk, smem);
    cluster_sync_all();
#pragma unroll 1
    for (int l = 24; l < 31; l++) {
        gemm_layer<2, 16>(cur, PPAD, c_off[l - 1], 1, wT2 + (size_t)i2 * 512 * 256,
                          b2 + i2 * 256, cur, c_off[l], 31 - l, b, nblk, smem);
        i2++;
        if (l < 30) cluster_sync_all();
    }
}

// ---------------- standalone GEMM (x-proj and Pc) ----------------
// out[b, m, n] = sum_c in[b, c, m] * wT[c*wld + n]
__global__ void __launch_bounds__(256) proj_gemm(
    const float* __restrict__ in, int in_row_len,
    const float* __restrict__ wT, int wld,
    float* __restrict__ out, int out_ld, int M_total) {
    constexpr int KC = 32;
    constexpr int NCH = 4;
    constexpr int WGS = 2 * KC * 64 + 2 * KC * 64;

    extern __shared__ float smem[];
    int tid = threadIdx.x;
    int wg = tid >> 7;
    int wtid = tid & 127;
    float* As = smem + wg * WGS;
    float* Bs = As + 2 * KC * 64;
    float* Red = smem + 2 * WGS;

    int b = blockIdx.z;
    int nblk = blockIdx.y * 64;
    int mblk = blockIdx.x * 64;
    int m0 = (wtid & 15) * 4;
    int n0 = (wtid >> 4) * 8;
    int am = wtid & 63;
    int ak0 = wtid >> 6;
    int bkb = wtid >> 4;
    int bn = (wtid & 15) * 4;

    const float* inb = in + (size_t)b * DCH * in_row_len;
    int kbase = wg * 128;

    float aA[16];
    float4 bB[4];
    auto gload = [&](int ch) {
        int c0k = kbase + ch * KC;
#pragma unroll
        for (int i = 0; i < 16; i++) {
            int k = c0k + ak0 + 2 * i;
            int mm = mblk + am;
            aA[i] = (mm < M_total) ? inb[(size_t)k * in_row_len + mm] : 0.f;
        }
#pragma unroll
        for (int i = 0; i < 4; i++) {
            int k = c0k + bkb + 8 * i;
            bB[i] = *(const float4*)&wT[(size_t)k * wld + nblk + bn];
        }
    };
    auto sts = [&](int buf) {
#pragma unroll
        for (int i = 0; i < 16; i++)
            As[buf * KC * 64 + (ak0 + 2 * i) * 64 + am] = aA[i];
#pragma unroll
        for (int i = 0; i < 4; i++)
            *(float4*)&Bs[buf * KC * 64 + (bkb + 8 * i) * 64 + bn] = bB[i];
    };

    unsigned long long acc[4][4];
#pragma unroll
    for (int mi = 0; mi < 4; mi++)
#pragma unroll
        for (int p = 0; p < 4; p++) acc[mi][p] = 0ULL;

    gload(0);
    sts(0);
    __syncthreads();

#pragma unroll 1
    for (int ch = 0; ch < NCH; ch++) {
        int buf = ch & 1;
        if (ch + 1 < NCH) gload(ch + 1);
#pragma unroll
        for (int k = 0; k < KC; k++) {
            float4 av = *(const float4*)&As[buf * KC * 64 + k * 64 + m0];
            const float* bp = &Bs[buf * KC * 64 + k * 64 + n0];
            ulonglong2 bl = *(const ulonglong2*)bp;
            ulonglong2 bh = *(const ulonglong2*)(bp + 4);
            float a[4] = {av.x, av.y, av.z, av.w};
#pragma unroll
            for (int mi = 0; mi < 4; mi++) {
                unsigned long long ad = dup2(a[mi]);
                fma2(acc[mi][0], ad, bl.x);
                fma2(acc[mi][1], ad, bl.y);
                fma2(acc[mi][2], ad, bh.x);
                fma2(acc[mi][3], ad, bh.y);
            }
        }
        if (ch + 1 < NCH) {
            sts(buf ^ 1);
            __syncthreads();
        }
    }

    float res[4][8];
#pragma unroll
    for (int mi = 0; mi < 4; mi++)
#pragma unroll
        for (int p = 0; p < 4; p++) {
            union { unsigned long long u; float2 f; } cv;
            cv.u = acc[mi][p];
            res[mi][2 * p] = cv.f.x;
            res[mi][2 * p + 1] = cv.f.y;
        }

    __syncthreads();
    if (wg == 1) {
#pragma unroll
        for (int mi = 0; mi < 4; mi++) {
            float* rp = &Red[(m0 + mi) * 64 + n0];
            *(float4*)rp = make_float4(res[mi][0], res[mi][1], res[mi][2], res[mi][3]);
            *(float4*)(rp + 4) =
                make_float4(res[mi][4], res[mi][5], res[mi][6], res[mi][7]);
        }
    }
    __syncthreads();
    if (wg != 0) return;

#pragma unroll
    for (int mi = 0; mi < 4; mi++) {
        const float* rp = &Red[(m0 + mi) * 64 + n0];
#pragma unroll
        for (int j = 0; j < 8; j++) res[mi][j] += rp[j];
    }

#pragma unroll
    for (int mi = 0; mi < 4; mi++) {
        int mm = mblk + m0 + mi;
        if (mm < M_total) {
            float* op = out + ((size_t)b * M_total + mm) * out_ld + nblk + n0;
            *(float4*)op = make_float4(res[mi][0], res[mi][1], res[mi][2], res[mi][3]);
            *(float4*)(op + 4) =
                make_float4(res[mi][4], res[mi][5], res[mi][6], res[mi][7]);
        }
    }
}

// ---------------- final output assembly ----------------
__global__ void __launch_bounds__(256) final_out(
    const float* __restrict__ P, const float* __restrict__ Pc,
    const float* __restrict__ vis_b, float* __restrict__ out) {
    int i = blockIdx.x;
    int b = blockIdx.y;
    int o = threadIdx.x;

    __shared__ int lut[64];
    if (o < 64) {
        int j = o;
        int d = j - i;
        int pg = -1;
        if (d >= 1 && d <= 15) {
            pg = c_off[d - 1] + i;
        } else if (d >= 17 && d <= 31 && ((d - 17) & 1) == 0 && (i & 1) == 0) {
            pg = c_off[15 + ((d - 17) >> 1)] + (i >> 1);
        } else if (d >= 35 && d <= 63 && ((d - 35) & 3) == 0 && (i & 3) == 0) {
            pg = c_off[23 + ((d - 35) >> 2)] + (i >> 2);
        }
        lut[j] = pg;
    }
    __syncthreads();

    float vb = __ldg(vis_b + o);
    float p1 = P[((size_t)b * NG + i) * 768 + o];
    float p2x = P[((size_t)b * NG + i) * 768 + 256 + o];
    const float* P3b = P + (size_t)b * NG * 768 + 512 + o;
    const float* Pcb = Pc + (size_t)b * PPAD * 256 + o;

    float accr[64];
#pragma unroll
    for (int j = 0; j < 64; j++) {
        float v = vb;
        if (j == i) {
            v += p1 + p2x + P3b[(size_t)j * 768];
        } else {
            int pg = lut[j];
            if (pg >= 0) v += p1 + Pcb[(size_t)pg * 256] + P3b[(size_t)j * 768];
        }
        accr[j] = v;
    }

    float4* op = (float4*)(out + (((size_t)b * DCH + o) * NG + i) * NG);
#pragma unroll
    for (int q = 0; q < 16; q++)
        op[q] = make_float4(accr[4 * q], accr[4 * q + 1], accr[4 * q + 2], accr[4 * q + 3]);
}

// ---------------- host ----------------
#define SMEM_CHAIN ((2 * (2 * 32 * 64 + 2 * 32 * 32)) * 4)               // 48 KB
#define SMEM_PROJ ((2 * (2 * 32 * 64 + 2 * 32 * 64) + 64 * 64) * 4)      // 80 KB

extern "C" void kernel_launch(void* const* d_in, const int* in_sizes, int n_in,
                              void* d_out, int out_size) {
    const float* x  = (const float*)d_in[0];
    const float* w2 = (const float*)d_in[1];
    const float* b2 = (const float*)d_in[2];
    const float* w3 = (const float*)d_in[3];
    const float* b3 = (const float*)d_in[4];
    const float* vw = (const float*)d_in[5];
    const float* vb = (const float*)d_in[6];
    float* out = (float*)d_out;

    float *wT2, *wT3, *wP, *cur, *Pc, *P;
    cudaGetSymbolAddress((void**)&wT2, g_wT2);
    cudaGetSymbolAddress((void**)&wT3, g_wT3);
    cudaGetSymbolAddress((void**)&wP, g_wP);
    cudaGetSymbolAddress((void**)&cur, g_cur);
    cudaGetSymbolAddress((void**)&Pc, g_Pc);
    cudaGetSymbolAddress((void**)&P, g_P);

    cudaFuncSetAttribute(chain_fused, cudaFuncAttributeMaxDynamicSharedMemorySize,
                         SMEM_CHAIN);
    cudaFuncSetAttribute(proj_gemm, cudaFuncAttributeMaxDynamicSharedMemorySize,
                         SMEM_PROJ);

    dim3 tb(32, 8);
    trans_k<<<dim3(512 / 32, 256 / 32, 29), tb>>>(w2, wT2, 256, 512, 512, 256,
                                                  (size_t)256 * 512, (size_t)256 * 512);
    trans_k<<<dim3(768 / 32, 256 / 32, 2), tb>>>(w3, wT3, 256, 768, 768, 256,
                                                 (size_t)256 * 768, (size_t)256 * 768);
    trans_k<<<dim3(256 / 32, 256 / 32, 3), tb>>>(vw, wP, 256, 256, 768, 768,
                                                 (size_t)256, (size_t)256);

    // fused chain: 32 clusters x 8 CTAs (one batch per cluster, N-slice 32 per CTA)
    chain_fused<<<256, 256, SMEM_CHAIN>>>(x, wT2, b2, wT3, b3, cur);

    // merged x projections: [B][64][768]
    proj_gemm<<<dim3(1, 12, BATCH), 256, SMEM_PROJ>>>(x, NG, wP, 768, P, 768, NG);
    // Pc: [B][1088][256]
    proj_gemm<<<dim3(17, 4, BATCH), 256, SMEM_PROJ>>>(cur, PPAD, wP + 256, 768, Pc,
                                                      256, PPAD);

    final_out<<<dim3(NG, BATCH), 256>>>(P, Pc, vb, out);
}

// round 9
// speedup vs baseline: 1.1329x; 1.1329x over previous
#include <cuda_runtime.h>
#include <cuda_bf16.h>
#include <cstdint>
#include <cstddef>

#define BATCH 32
#define DCH 256
#define NG 64
#define PPAD 1088   // padded total conv positions (17 * 64)

__constant__ int c_off[31] = {0,64,128,192,252,312,372,432,488,544,600,656,708,760,812,
                              864,888,912,936,960,980,1000,1020,
                              1040,1048,1056,1064,1072,1076,1080,1084};

// ---------------- scratch ----------------
__device__ float g_wT2[29 * 512 * 256];
__device__ float g_wT3[2 * 768 * 256];
__device__ float g_wP[256 * 768];
__device__ float g_cur[(size_t)BATCH * DCH * PPAD];
__device__ float g_Pc[(size_t)BATCH * PPAD * DCH];
__device__ float g_P[(size_t)BATCH * NG * 768];
// bf16-split transposed activations [B][PPAD][256] (hi/lo), stored as uint4
__device__ uint4 g_curT_hi[(size_t)BATCH * PPAD * 256 / 8];
__device__ uint4 g_curT_lo[(size_t)BATCH * PPAD * 256 / 8];
// bf16-split B for Pc: [256 n][256 c]
__device__ uint4 g_wB_hi[256 * 256 / 8];
__device__ uint4 g_wB_lo[256 * 256 / 8];

// ---------------- f32x2 helpers ----------------
__device__ __forceinline__ void fma2(unsigned long long& d, unsigned long long a,
                                     unsigned long long b) {
    asm("fma.rn.f32x2 %0, %1, %2, %3;" : "=l"(d) : "l"(a), "l"(b), "l"(d));
}
__device__ __forceinline__ unsigned long long dup2(float x) {
    unsigned long long r;
    unsigned int xi = __float_as_uint(x);
    asm("mov.b64 %0, {%1, %1};" : "=l"(r) : "r"(xi));
    return r;
}
__device__ __forceinline__ void cluster_sync_all() {
    asm volatile("barrier.cluster.arrive.aligned;" ::: "memory");
    asm volatile("barrier.cluster.wait.aligned;" ::: "memory");
}

// ---------------- mma.sync bf16 helper (sm_80+, legal on base compute_103) ------
__device__ __forceinline__ void mma_bf16(float* d, const uint32_t* a,
                                         const uint32_t* b) {
    asm volatile(
        "mma.sync.aligned.m16n8k16.row.col.f32.bf16.bf16.f32 "
        "{%0,%1,%2,%3}, {%4,%5,%6,%7}, {%8,%9}, {%0,%1,%2,%3};"
        : "+f"(d[0]), "+f"(d[1]), "+f"(d[2]), "+f"(d[3])
        : "r"(a[0]), "r"(a[1]), "r"(a[2]), "r"(a[3]), "r"(b[0]), "r"(b[1]));
}

// ---------------- generalized transpose ----------------
__global__ void trans_k(const float* __restrict__ in, float* __restrict__ out,
                        int R, int C, int in_ld, int out_ld,
                        size_t in_bs, size_t out_bs) {
    __shared__ float tile[32][33];
    int bat = blockIdx.z;
    int c0 = blockIdx.x * 32, r0 = blockIdx.y * 32;
    const float* ib = in + (size_t)bat * in_bs;
    float* ob = out + (size_t)bat * out_bs;
    int tx = threadIdx.x, ty = threadIdx.y;
#pragma unroll
    for (int s = 0; s < 32; s += 8) {
        int r = r0 + ty + s, c = c0 + tx;
        if (r < R && c < C) tile[ty + s][tx] = ib[(size_t)r * in_ld + c];
    }
    __syncthreads();
#pragma unroll
    for (int s = 0; s < 32; s += 8) {
        int c = c0 + ty + s, r = r0 + tx;
        if (c < C && r < R) ob[(size_t)c * out_ld + r] = tile[tx][ty + s];
    }
}

// ---------------- split cur -> curT (bf16 hi/lo, pos-major) ----------------
__global__ void split_curT(const float* __restrict__ cur,
                           __nv_bfloat16* __restrict__ hi,
                           __nv_bfloat16* __restrict__ lo) {
    __shared__ float t[32][33];
    int b = blockIdx.z;
    int p0 = blockIdx.x * 32, ch0 = blockIdx.y * 32;
    int tx = threadIdx.x, ty = threadIdx.y;
#pragma unroll
    for (int s = 0; s < 32; s += 8) {
        int c = ch0 + ty + s;
        t[ty + s][tx] = cur[((size_t)b * DCH + c) * PPAD + p0 + tx];
    }
    __syncthreads();
#pragma unroll
    for (int s = 0; s < 32; s += 8) {
        int p = p0 + ty + s, c = ch0 + tx;
        float v = t[tx][ty + s];
        __nv_bfloat16 h = __float2bfloat16(v);
        __nv_bfloat16 l = __float2bfloat16(v - __bfloat162float(h));
        size_t o = ((size_t)b * PPAD + p) * 256 + c;
        hi[o] = h;
        lo[o] = l;
    }
}

// ---------------- split vis_w middle slice -> B (bf16 hi/lo) ----------------
__global__ void split_B(const float* __restrict__ vw,
                        __nv_bfloat16* __restrict__ hi,
                        __nv_bfloat16* __restrict__ lo) {
    int n = blockIdx.x, c = threadIdx.x;
    float v = vw[(size_t)n * 768 + 256 + c];
    __nv_bfloat16 h = __float2bfloat16(v);
    __nv_bfloat16 l = __float2bfloat16(v - __bfloat162float(h));
    hi[n * 256 + c] = h;
    lo[n * 256 + c] = l;
}

// ---------------- Pc GEMM via mma.sync bf16x3 ----------------
// Pc[b, m, n] = sum_c curT[b,m,c] * wB[n,c]
// CTA: 64(M) x 64(N) tile, K=256 in smem; 4 warps (2x2), warp tile 32x32.
// smem rows padded to 264 bf16 (132 words): conflict-free fragment reads.
#define ROWB 528                 // bytes per smem row
#define ABUF (64 * ROWB)         // 33792 B per buffer
#define SM_AH 0
#define SM_AL ABUF
#define SM_BH (2 * ABUF)
#define SM_BL (3 * ABUF)
#define PC_SMEM (4 * ABUF)       // 132 KB

__global__ void __launch_bounds__(128, 1)
pc_mma(const uint4* __restrict__ Ahi, const uint4* __restrict__ Alo,
       const uint4* __restrict__ Bhi, const uint4* __restrict__ Blo,
       float* __restrict__ Pc) {
    extern __shared__ char sm[];
    int tid = threadIdx.x;
    int warp = tid >> 5, lane = tid & 31;
    int b = blockIdx.z, mt = blockIdx.x, nb = blockIdx.y * 64;

    // cooperative loads: A 64 rows (hi+lo), B 64 rows (hi+lo); 32 uint4/row
    {
        size_t srcb = ((size_t)b * PPAD + mt * 64) * 32;
#pragma unroll
        for (int i = 0; i < 16; i++) {
            int e = tid + 128 * i;
            int r = e >> 5, q = e & 31;
            int dst = r * ROWB + q * 16;
            *(uint4*)(sm + SM_AH + dst) = Ahi[srcb + (size_t)r * 32 + q];
            *(uint4*)(sm + SM_AL + dst) = Alo[srcb + (size_t)r * 32 + q];
        }
#pragma unroll
        for (int i = 0; i < 16; i++) {
            int e = tid + 128 * i;
            int r = e >> 5, q = e & 31;
            int dst = r * ROWB + q * 16;
            *(uint4*)(sm + SM_BH + dst) = Bhi[(size_t)(nb + r) * 32 + q];
            *(uint4*)(sm + SM_BL + dst) = Blo[(size_t)(nb + r) * 32 + q];
        }
    }
    __syncthreads();

    int g = lane >> 2, t = lane & 3;
    int wm = (warp >> 1) * 32;   // warp M offset in tile
    int wn = (warp & 1) * 32;    // warp N offset in tile

    float acc[2][4][4];
#pragma unroll
    for (int mi = 0; mi < 2; mi++)
#pragma unroll
        for (int ni = 0; ni < 4; ni++)
#pragma unroll
            for (int p = 0; p < 4; p++) acc[mi][ni][p] = 0.f;

    const uint32_t* AH = (const uint32_t*)(sm + SM_AH);
    const uint32_t* AL = (const uint32_t*)(sm + SM_AL);
    const uint32_t* BH = (const uint32_t*)(sm + SM_BH);
    const uint32_t* BL = (const uint32_t*)(sm + SM_BL);

#pragma unroll 1
    for (int pass = 0; pass < 3; pass++) {
        const uint32_t* Aw = (pass == 2) ? AL : AH;
        const uint32_t* Bw = (pass == 1) ? BL : BH;
#pragma unroll
        for (int ks = 0; ks < 16; ks++) {
            int kw = ks * 8;  // word offset within row (8 words = 16 bf16)
            uint32_t af[2][4], bf[4][2];
#pragma unroll
            for (int mi = 0; mi < 2; mi++) {
                int row = wm + mi * 16 + g;
                af[mi][0] = Aw[row * 132 + kw + t];
                af[mi][1] = Aw[(row + 8) * 132 + kw + t];
                af[mi][2] = Aw[row * 132 + kw + t + 4];
                af[mi][3] = Aw[(row + 8) * 132 + kw + t + 4];
            }
#pragma unroll
            for (int ni = 0; ni < 4; ni++) {
                int nr = wn + ni * 8 + g;
                bf[ni][0] = Bw[nr * 132 + kw + t];
                bf[ni][1] = Bw[nr * 132 + kw + t + 4];
            }
#pragma unroll
            for (int mi = 0; mi < 2; mi++)
#pragma unroll
                for (int ni = 0; ni < 4; ni++) mma_bf16(acc[mi][ni], af[mi], bf[ni]);
        }
    }

    // store: D[g][2t], D[g][2t+1] and D[g+8][2t], D[g+8][2t+1]
#pragma unroll
    for (int mi = 0; mi < 2; mi++) {
        int m = mt * 64 + wm + mi * 16 + g;
#pragma unroll
        for (int ni = 0; ni < 4; ni++) {
            int n = nb + wn + ni * 8 + 2 * t;
            float* p0 = Pc + ((size_t)b * PPAD + m) * 256 + n;
            float* p1 = Pc + ((size_t)b * PPAD + m + 8) * 256 + n;
            *(float2*)p0 = make_float2(acc[mi][ni][0], acc[mi][ni][1]);
            *(float2*)p1 = make_float2(acc[mi][ni][2], acc[mi][ni][3]);
        }
    }
}

// ---------------- per-layer GEMM body (R6 proven internals) ----------------
template <int KSZ, int TM>
__device__ __forceinline__ void gemm_layer(
    const float* __restrict__ in, int in_row_len, int in_off, int cstride,
    const float* __restrict__ wT, const float* __restrict__ bias,
    float* __restrict__ outp, int out_off, int M_total,
    int b, int nblk, float* smem) {
    constexpr int KTOT = KSZ * 256;
    constexpr int KH = KTOT / 2;
    constexpr int KC = (KSZ == 3) ? 24 : 32;
    constexpr int NCH = KH / KC;
    constexpr int AG = 128 / TM;
    constexpr int NA = KC / AG;
    constexpr int NB = KC / 8;
    constexpr int MR = TM / 16;
    constexpr int WGS = 2 * KC * TM + 2 * KC * 64;

    int tid = threadIdx.x;
    int wg = tid >> 7;
    int wtid = tid & 127;
    float* As = smem + wg * WGS;
    float* Bs = As + 2 * KC * TM;
    float* Red = smem + 2 * WGS;

    int m0 = (wtid & 15) * MR;
    int n0 = (wtid >> 4) * 8;
    int am = wtid % TM;
    int ak0 = wtid / TM;
    int bkb = wtid >> 4;
    int bn = (wtid & 15) * 4;

    const float* inb = in + (size_t)b * DCH * in_row_len + in_off;
    int kbase = wg * KH;

    float aA[NA];
    float4 bB[NB];
    auto gload = [&](int ch) {
        int c0k = kbase + ch * KC;
#pragma unroll
        for (int i = 0; i < NA; i++) {
            int k = c0k + ak0 + AG * i;
            int c = k / KSZ;
            int kk = k - c * KSZ;
            aA[i] = (am < M_total)
                        ? inb[(size_t)c * in_row_len + am * cstride + kk]
                        : 0.f;
        }
#pragma unroll
        for (int i = 0; i < NB; i++) {
            int k = c0k + bkb + 8 * i;
            bB[i] = *(const float4*)&wT[(size_t)k * 256 + nblk + bn];
        }
    };
    auto sts = [&](int buf) {
#pragma unroll
        for (int i = 0; i < NA; i++)
            As[buf * KC * TM + (ak0 + AG * i) * TM + am] = aA[i];
#pragma unroll
        for (int i = 0; i < NB; i++)
            *(float4*)&Bs[buf * KC * 64 + (bkb + 8 * i) * 64 + bn] = bB[i];
    };

    unsigned long long acc[MR][4];
#pragma unroll
    for (int mi = 0; mi < MR; mi++)
#pragma unroll
        for (int p = 0; p < 4; p++) acc[mi][p] = 0ULL;

    gload(0);
    sts(0);
    __syncthreads();

#pragma unroll 1
    for (int ch = 0; ch < NCH; ch++) {
        int buf = ch & 1;
        if (ch + 1 < NCH) gload(ch + 1);
#pragma unroll
        for (int k = 0; k < KC; k++) {
            float a[MR];
            const float* ap = &As[buf * KC * TM + k * TM + m0];
            if (MR == 4) {
                float4 v = *(const float4*)ap;
                a[0] = v.x; a[1] = v.y; a[2] = v.z; a[3] = v.w;
            } else if (MR == 2) {
                float2 v = *(const float2*)ap;
                a[0] = v.x; a[1] = v.y;
            } else {
                a[0] = *ap;
            }
            const float* bp = &Bs[buf * KC * 64 + k * 64 + n0];
            ulonglong2 bl = *(const ulonglong2*)bp;
            ulonglong2 bh = *(const ulonglong2*)(bp + 4);
#pragma unroll
            for (int mi = 0; mi < MR; mi++) {
                unsigned long long ad = dup2(a[mi]);
                fma2(acc[mi][0], ad, bl.x);
                fma2(acc[mi][1], ad, bl.y);
                fma2(acc[mi][2], ad, bh.x);
                fma2(acc[mi][3], ad, bh.y);
            }
        }
        if (ch + 1 < NCH) {
            sts(buf ^ 1);
            __syncthreads();
        }
    }

    float res[MR][8];
#pragma unroll
    for (int mi = 0; mi < MR; mi++)
#pragma unroll
        for (int p = 0; p < 4; p++) {
            union { unsigned long long u; float2 f; } cv;
            cv.u = acc[mi][p];
            res[mi][2 * p] = cv.f.x;
            res[mi][2 * p + 1] = cv.f.y;
        }

    __syncthreads();
    if (wg == 1) {
#pragma unroll
        for (int mi = 0; mi < MR; mi++) {
            float* rp = &Red[(m0 + mi) * 64 + n0];
            *(float4*)rp = make_float4(res[mi][0], res[mi][1], res[mi][2], res[mi][3]);
            *(float4*)(rp + 4) =
                make_float4(res[mi][4], res[mi][5], res[mi][6], res[mi][7]);
        }
    }
    __syncthreads();

    if (wg == 0) {
#pragma unroll
        for (int mi = 0; mi < MR; mi++) {
            const float* rp = &Red[(m0 + mi) * 64 + n0];
#pragma unroll
            for (int j = 0; j < 8; j++) res[mi][j] += rp[j];
        }
#pragma unroll
        for (int j = 0; j < 8; j++) {
            int n = nblk + n0 + j;
            float bv = __ldg(bias + n);
            float* orow = outp + ((size_t)b * DCH + n) * PPAD + out_off + m0;
#pragma unroll
            for (int mi = 0; mi < MR; mi++)
                if (m0 + mi < M_total) orow[mi] = res[mi][j] + bv;
        }
    }
    __syncthreads();
}

// ---------------- fused 31-layer chain: 4-CTA clusters (R6 proven) ----------------
__global__ void __launch_bounds__(256, 1) __cluster_dims__(4, 1, 1)
chain_fused(const float* __restrict__ x,
            const float* __restrict__ wT2, const float* __restrict__ b2,
            const float* __restrict__ wT3, const float* __restrict__ b3,
            float* __restrict__ cur) {
    extern __shared__ float smemf[];
    int b = blockIdx.x >> 2;
    int nblk = (blockIdx.x & 3) * 64;

    int i2 = 0;
#pragma unroll 1
    for (int l = 0; l < 15; l++) {
        const float* in = (l == 0) ? x : cur;
        int irl = (l == 0) ? NG : PPAD;
        int ioff = (l == 0) ? 0 : c_off[l - 1];
        gemm_layer<2, 64>(in, irl, ioff, 1, wT2 + (size_t)i2 * 512 * 256,
                          b2 + i2 * 256, cur, c_off[l], 63 - l, b, nblk, smemf);
        i2++;
        cluster_sync_all();
    }
    gemm_layer<3, 32>(cur, PPAD, c_off[14], 2, wT3, b3, cur, c_off[15], 24, b, nblk,
                      smemf);
    cluster_sync_all();
#pragma unroll 1
    for (int l = 16; l < 23; l++) {
        gemm_layer<2, 32>(cur, PPAD, c_off[l - 1], 1, wT2 + (size_t)i2 * 512 * 256,
                          b2 + i2 * 256, cur, c_off[l], 39 - l, b, nblk, smemf);
        i2++;
        cluster_sync_all();
    }
    gemm_layer<3, 16>(cur, PPAD, c_off[22], 2, wT3 + (size_t)768 * 256, b3 + 256, cur,
                      c_off[23], 8, b, nblk, smemf);
    cluster_sync_all();
#pragma unroll 1
    for (int l = 24; l < 31; l++) {
        gemm_layer<2, 16>(cur, PPAD, c_off[l - 1], 1, wT2 + (size_t)i2 * 512 * 256,
                          b2 + i2 * 256, cur, c_off[l], 31 - l, b, nblk, smemf);
        i2++;
        if (l < 30) cluster_sync_all();
    }
}

// ---------------- x-projection GEMM (fp32, R6 proven) ----------------
__global__ void __launch_bounds__(256) proj_gemm(
    const float* __restrict__ in, int in_row_len,
    const float* __restrict__ wT, int wld,
    float* __restrict__ out, int out_ld, int M_total) {
    constexpr int KC = 32;
    constexpr int NCH = 4;
    constexpr int WGS = 2 * KC * 64 + 2 * KC * 64;

    extern __shared__ float smemf[];
    int tid = threadIdx.x;
    int wg = tid >> 7;
    int wtid = tid & 127;
    float* As = smemf + wg * WGS;
    float* Bs = As + 2 * KC * 64;
    float* Red = smemf + 2 * WGS;

    int b = blockIdx.z;
    int nblk = blockIdx.y * 64;
    int mblk = blockIdx.x * 64;
    int m0 = (wtid & 15) * 4;
    int n0 = (wtid >> 4) * 8;
    int am = wtid & 63;
    int ak0 = wtid >> 6;
    int bkb = wtid >> 4;
    int bn = (wtid & 15) * 4;

    const float* inb = in + (size_t)b * DCH * in_row_len;
    int kbase = wg * 128;

    float aA[16];
    float4 bB[4];
    auto gload = [&](int ch) {
        int c0k = kbase + ch * KC;
#pragma unroll
        for (int i = 0; i < 16; i++) {
            int k = c0k + ak0 + 2 * i;
            int mm = mblk + am;
            aA[i] = (mm < M_total) ? inb[(size_t)k * in_row_len + mm] : 0.f;
        }
#pragma unroll
        for (int i = 0; i < 4; i++) {
            int k = c0k + bkb + 8 * i;
            bB[i] = *(const float4*)&wT[(size_t)k * wld + nblk + bn];
        }
    };
    auto sts = [&](int buf) {
#pragma unroll
        for (int i = 0; i < 16; i++)
            As[buf * KC * 64 + (ak0 + 2 * i) * 64 + am] = aA[i];
#pragma unroll
        for (int i = 0; i < 4; i++)
            *(float4*)&Bs[buf * KC * 64 + (bkb + 8 * i) * 64 + bn] = bB[i];
    };

    unsigned long long acc[4][4];
#pragma unroll
    for (int mi = 0; mi < 4; mi++)
#pragma unroll
        for (int p = 0; p < 4; p++) acc[mi][p] = 0ULL;

    gload(0);
    sts(0);
    __syncthreads();

#pragma unroll 1
    for (int ch = 0; ch < NCH; ch++) {
        int buf = ch & 1;
        if (ch + 1 < NCH) gload(ch + 1);
#pragma unroll
        for (int k = 0; k < KC; k++) {
            float4 av = *(const float4*)&As[buf * KC * 64 + k * 64 + m0];
            const float* bp = &Bs[buf * KC * 64 + k * 64 + n0];
            ulonglong2 bl = *(const ulonglong2*)bp;
            ulonglong2 bh = *(const ulonglong2*)(bp + 4);
            float a[4] = {av.x, av.y, av.z, av.w};
#pragma unroll
            for (int mi = 0; mi < 4; mi++) {
                unsigned long long ad = dup2(a[mi]);
                fma2(acc[mi][0], ad, bl.x);
                fma2(acc[mi][1], ad, bl.y);
                fma2(acc[mi][2], ad, bh.x);
                fma2(acc[mi][3], ad, bh.y);
            }
        }
        if (ch + 1 < NCH) {
            sts(buf ^ 1);
            __syncthreads();
        }
    }

    float res[4][8];
#pragma unroll
    for (int mi = 0; mi < 4; mi++)
#pragma unroll
        for (int p = 0; p < 4; p++) {
            union { unsigned long long u; float2 f; } cv;
            cv.u = acc[mi][p];
            res[mi][2 * p] = cv.f.x;
            res[mi][2 * p + 1] = cv.f.y;
        }

    __syncthreads();
    if (wg == 1) {
#pragma unroll
        for (int mi = 0; mi < 4; mi++) {
            float* rp = &Red[(m0 + mi) * 64 + n0];
            *(float4*)rp = make_float4(res[mi][0], res[mi][1], res[mi][2], res[mi][3]);
            *(float4*)(rp + 4) =
                make_float4(res[mi][4], res[mi][5], res[mi][6], res[mi][7]);
        }
    }
    __syncthreads();
    if (wg != 0) return;

#pragma unroll
    for (int mi = 0; mi < 4; mi++) {
        const float* rp = &Red[(m0 + mi) * 64 + n0];
#pragma unroll
        for (int j = 0; j < 8; j++) res[mi][j] += rp[j];
    }

#pragma unroll
    for (int mi = 0; mi < 4; mi++) {
        int mm = mblk + m0 + mi;
        if (mm < M_total) {
            float* op = out + ((size_t)b * M_total + mm) * out_ld + nblk + n0;
            *(float4*)op = make_float4(res[mi][0], res[mi][1], res[mi][2], res[mi][3]);
            *(float4*)(op + 4) =
                make_float4(res[mi][4], res[mi][5], res[mi][6], res[mi][7]);
        }
    }
}

// ---------------- final output assembly ----------------
__global__ void __launch_bounds__(256) final_out(
    const float* __restrict__ P, const float* __restrict__ Pc,
    const float* __restrict__ vis_b, float* __restrict__ out) {
    int i = blockIdx.x;
    int b = blockIdx.y;
    int o = threadIdx.x;

    __shared__ int lut[64];
    if (o < 64) {
        int j = o;
        int d = j - i;
        int pg = -1;
        if (d >= 1 && d <= 15) {
            pg = c_off[d - 1] + i;
        } else if (d >= 17 && d <= 31 && ((d - 17) & 1) == 0 && (i & 1) == 0) {
            pg = c_off[15 + ((d - 17) >> 1)] + (i >> 1);
        } else if (d >= 35 && d <= 63 && ((d - 35) & 3) == 0 && (i & 3) == 0) {
            pg = c_off[23 + ((d - 35) >> 2)] + (i >> 2);
        }
        lut[j] = pg;
    }
    __syncthreads();

    float vb = __ldg(vis_b + o);
    float p1 = P[((size_t)b * NG + i) * 768 + o];
    float p2x = P[((size_t)b * NG + i) * 768 + 256 + o];
    const float* P3b = P + (size_t)b * NG * 768 + 512 + o;
    const float* Pcb = Pc + (size_t)b * PPAD * 256 + o;

    float accr[64];
#pragma unroll
    for (int j = 0; j < 64; j++) {
        float v = vb;
        if (j == i) {
            v += p1 + p2x + P3b[(size_t)j * 768];
        } else {
            int pg = lut[j];
            if (pg >= 0) v += p1 + Pcb[(size_t)pg * 256] + P3b[(size_t)j * 768];
        }
        accr[j] = v;
    }

    float4* op = (float4*)(out + (((size_t)b * DCH + o) * NG + i) * NG);
#pragma unroll
    for (int q = 0; q < 16; q++)
        op[q] = make_float4(accr[4 * q], accr[4 * q + 1], accr[4 * q + 2], accr[4 * q + 3]);
}

// ---------------- host ----------------
#define SMEM_CHAIN ((2 * (2 * 32 * 64 + 2 * 32 * 64) + 64 * 64) * 4)  // 80 KB
#define SMEM_PROJ SMEM_CHAIN

extern "C" void kernel_launch(void* const* d_in, const int* in_sizes, int n_in,
                              void* d_out, int out_size) {
    const float* x  = (const float*)d_in[0];
    const float* w2 = (const float*)d_in[1];
    const float* b2 = (const float*)d_in[2];
    const float* w3 = (const float*)d_in[3];
    const float* b3 = (const float*)d_in[4];
    const float* vw = (const float*)d_in[5];
    const float* vb = (const float*)d_in[6];
    float* out = (float*)d_out;

    float *wT2, *wT3, *wP, *cur, *Pc, *P;
    uint4 *cthi, *ctlo, *wbhi, *wblo;
    cudaGetSymbolAddress((void**)&wT2, g_wT2);
    cudaGetSymbolAddress((void**)&wT3, g_wT3);
    cudaGetSymbolAddress((void**)&wP, g_wP);
    cudaGetSymbolAddress((void**)&cur, g_cur);
    cudaGetSymbolAddress((void**)&Pc, g_Pc);
    cudaGetSymbolAddress((void**)&P, g_P);
    cudaGetSymbolAddress((void**)&cthi, g_curT_hi);
    cudaGetSymbolAddress((void**)&ctlo, g_curT_lo);
    cudaGetSymbolAddress((void**)&wbhi, g_wB_hi);
    cudaGetSymbolAddress((void**)&wblo, g_wB_lo);

    cudaFuncSetAttribute(chain_fused, cudaFuncAttributeMaxDynamicSharedMemorySize,
                         SMEM_CHAIN);
    cudaFuncSetAttribute(proj_gemm, cudaFuncAttributeMaxDynamicSharedMemorySize,
                         SMEM_PROJ);
    cudaFuncSetAttribute(pc_mma, cudaFuncAttributeMaxDynamicSharedMemorySize, PC_SMEM);

    dim3 tb(32, 8);
    trans_k<<<dim3(512 / 32, 256 / 32, 29), tb>>>(w2, wT2, 256, 512, 512, 256,
                                                  (size_t)256 * 512, (size_t)256 * 512);
    trans_k<<<dim3(768 / 32, 256 / 32, 2), tb>>>(w3, wT3, 256, 768, 768, 256,
                                                 (size_t)256 * 768, (size_t)256 * 768);
    trans_k<<<dim3(256 / 32, 256 / 32, 3), tb>>>(vw, wP, 256, 256, 768, 768,
                                                 (size_t)256, (size_t)256);
    split_B<<<256, 256>>>(vw, (__nv_bfloat16*)wbhi, (__nv_bfloat16*)wblo);

    // fused chain (R6 config): 32 clusters x 4 CTAs
    chain_fused<<<128, 256, SMEM_CHAIN>>>(x, wT2, b2, wT3, b3, cur);

    // transpose + bf16-split the chain outputs for the mma Pc GEMM
    split_curT<<<dim3(PPAD / 32, 8, BATCH), tb>>>(cur, (__nv_bfloat16*)cthi,
                                                  (__nv_bfloat16*)ctlo);

    // merged x projections (fp32): [B][64][768]
    proj_gemm<<<dim3(1, 12, BATCH), 256, SMEM_PROJ>>>(x, NG, wP, 768, P, 768, NG);

    // Pc via mma.sync bf16x3: grid (17 M-tiles, 4 N-tiles, 32 batches)
    pc_mma<<<dim3(PPAD / 64, 4, BATCH), 128, PC_SMEM>>>(cthi, ctlo, wbhi, wblo, Pc);

    final_out<<<dim3(NG, BATCH), 256>>>(P, Pc, vb, out);
}

// round 10
// speedup vs baseline: 1.5532x; 1.3709x over previous
#include <cuda_runtime.h>
#include <cuda_bf16.h>
#include <cstdint>
#include <cstddef>

#define BATCH 32
#define DCH 256
#define NG 64
#define PPAD 1088   // padded total conv positions (17 * 64)

__constant__ int c_off[31] = {0,64,128,192,252,312,372,432,488,544,600,656,708,760,812,
                              864,888,912,936,960,980,1000,1020,
                              1040,1048,1056,1064,1072,1076,1080,1084};
// per-layer tables for the mma chain
__constant__ int c_tb[31]  = {0,2,4,6,8,10,12,14,16,18,20,22,24,26,28, 30,
                              33,35,37,39,41,43,45, 47, 50,52,54,56,58,60,62};
__constant__ int c_taps[31] = {2,2,2,2,2,2,2,2,2,2,2,2,2,2,2, 3, 2,2,2,2,2,2,2, 3,
                               2,2,2,2,2,2,2};
__constant__ int c_cs[31]   = {1,1,1,1,1,1,1,1,1,1,1,1,1,1,1, 2, 1,1,1,1,1,1,1, 2,
                               1,1,1,1,1,1,1};
__constant__ int c_M[31]    = {63,62,61,60,59,58,57,56,55,54,53,52,51,50,49, 24,
                               23,22,21,20,19,18,17, 8, 7,6,5,4,3,2,1};
__constant__ int c_bi[31]   = {0,1,2,3,4,5,6,7,8,9,10,11,12,13,14, 0,
                               15,16,17,18,19,20,21, 1, 22,23,24,25,26,27,28};
__constant__ int c_isk3[31] = {0,0,0,0,0,0,0,0,0,0,0,0,0,0,0, 1, 0,0,0,0,0,0,0, 1,
                               0,0,0,0,0,0,0};
__constant__ int c_tb2[29]  = {0,2,4,6,8,10,12,14,16,18,20,22,24,26,28,
                               33,35,37,39,41,43,45, 50,52,54,56,58,60,62};

// ---------------- scratch ----------------
__device__ float g_wP[256 * 768];
__device__ float g_Pc[(size_t)BATCH * PPAD * DCH];
__device__ float g_P[(size_t)BATCH * NG * 768];
// activations (bf16 hi/lo, pos-major [B][PPAD][256])
__device__ uint4 g_act_hi[(size_t)BATCH * PPAD * 256 / 8];
__device__ uint4 g_act_lo[(size_t)BATCH * PPAD * 256 / 8];
// input x split [B][64][256]
__device__ uint4 g_xa_hi[(size_t)BATCH * 64 * 256 / 8];
__device__ uint4 g_xa_lo[(size_t)BATCH * 64 * 256 / 8];
// per-tap weights [64 taps][256 n][256 c] bf16 hi/lo
__device__ uint4 g_w_hi[64 * 256 * 256 / 8];
__device__ uint4 g_w_lo[64 * 256 * 256 / 8];
// bf16-split B for Pc: [256 n][256 c]
__device__ uint4 g_wB_hi[256 * 256 / 8];
__device__ uint4 g_wB_lo[256 * 256 / 8];

// ---------------- f32x2 helpers (proj_gemm) ----------------
__device__ __forceinline__ void fma2(unsigned long long& d, unsigned long long a,
                                     unsigned long long b) {
    asm("fma.rn.f32x2 %0, %1, %2, %3;" : "=l"(d) : "l"(a), "l"(b), "l"(d));
}
__device__ __forceinline__ unsigned long long dup2(float x) {
    unsigned long long r;
    unsigned int xi = __float_as_uint(x);
    asm("mov.b64 %0, {%1, %1};" : "=l"(r) : "r"(xi));
    return r;
}
__device__ __forceinline__ void cluster_sync_all() {
    asm volatile("barrier.cluster.arrive.aligned;" ::: "memory");
    asm volatile("barrier.cluster.wait.aligned;" ::: "memory");
}

// ---------------- mma.sync bf16 helper ----------------
__device__ __forceinline__ void mma_bf16(float* d, const uint32_t* a,
                                         const uint32_t* b) {
    asm volatile(
        "mma.sync.aligned.m16n8k16.row.col.f32.bf16.bf16.f32 "
        "{%0,%1,%2,%3}, {%4,%5,%6,%7}, {%8,%9}, {%0,%1,%2,%3};"
        : "+f"(d[0]), "+f"(d[1]), "+f"(d[2]), "+f"(d[3])
        : "r"(a[0]), "r"(a[1]), "r"(a[2]), "r"(a[3]), "r"(b[0]), "r"(b[1]));
}

// ---------------- generalized transpose (for wP) ----------------
__global__ void trans_k(const float* __restrict__ in, float* __restrict__ out,
                        int R, int C, int in_ld, int out_ld,
                        size_t in_bs, size_t out_bs) {
    __shared__ float tile[32][33];
    int bat = blockIdx.z;
    int c0 = blockIdx.x * 32, r0 = blockIdx.y * 32;
    const float* ib = in + (size_t)bat * in_bs;
    float* ob = out + (size_t)bat * out_bs;
    int tx = threadIdx.x, ty = threadIdx.y;
#pragma unroll
    for (int s = 0; s < 32; s += 8) {
        int r = r0 + ty + s, c = c0 + tx;
        if (r < R && c < C) tile[ty + s][tx] = ib[(size_t)r * in_ld + c];
    }
    __syncthreads();
#pragma unroll
    for (int s = 0; s < 32; s += 8) {
        int c = c0 + ty + s, r = r0 + tx;
        if (c < C && r < R) ob[(size_t)c * out_ld + r] = tile[tx][ty + s];
    }
}

// ---------------- x -> xact split (pos-major bf16 hi/lo) ----------------
__global__ void xsplit(const float* __restrict__ x,
                       __nv_bfloat16* __restrict__ hi,
                       __nv_bfloat16* __restrict__ lo) {
    __shared__ float t[32][33];
    int b = blockIdx.z;
    int p0 = blockIdx.x * 32, ch0 = blockIdx.y * 32;
    int tx = threadIdx.x, ty = threadIdx.y;
#pragma unroll
    for (int s = 0; s < 32; s += 8) {
        int c = ch0 + ty + s;
        t[ty + s][tx] = x[((size_t)b * DCH + c) * NG + p0 + tx];
    }
    __syncthreads();
#pragma unroll
    for (int s = 0; s < 32; s += 8) {
        int p = p0 + ty + s, c = ch0 + tx;
        float v = t[tx][ty + s];
        __nv_bfloat16 h = __float2bfloat16(v);
        __nv_bfloat16 l = __float2bfloat16(v - __bfloat162float(h));
        size_t o = ((size_t)b * NG + p) * 256 + c;
        hi[o] = h;
        lo[o] = l;
    }
}

// ---------------- weight split: w2/w3 -> per-tap [64][256n][256c] bf16 ----------
#define W2TOT (29 * 256 * 256 * 2)
#define WTOT (W2TOT + 2 * 256 * 256 * 3)
__global__ void wsplit(const float* __restrict__ w2, const float* __restrict__ w3,
                       __nv_bfloat16* __restrict__ hi,
                       __nv_bfloat16* __restrict__ lo) {
    for (int idx = blockIdx.x * blockDim.x + threadIdx.x; idx < WTOT;
         idx += gridDim.x * blockDim.x) {
        float v;
        int tap, n, c;
        if (idx < W2TOT) {
            int i2 = idx >> 17;
            int r = idx & 0x1FFFF;
            n = r >> 9;
            int r2 = r & 511;
            c = r2 >> 1;
            int kk = r2 & 1;
            v = w2[idx];
            tap = c_tb2[i2] + kk;
        } else {
            int j = idx - W2TOT;
            int i3 = j / 196608;
            int r = j % 196608;
            n = r / 768;
            int r2 = r % 768;
            c = r2 / 3;
            int kk = r2 % 3;
            v = w3[j];
            tap = (i3 ? 47 : 30) + kk;
        }
        size_t dst = (size_t)tap * 65536 + (size_t)n * 256 + c;
        __nv_bfloat16 h = __float2bfloat16(v);
        __nv_bfloat16 l = __float2bfloat16(v - __bfloat162float(h));
        hi[dst] = h;
        lo[dst] = l;
    }
}

// ---------------- split vis_w middle slice -> B for Pc ----------------
__global__ void split_B(const float* __restrict__ vw,
                        __nv_bfloat16* __restrict__ hi,
                        __nv_bfloat16* __restrict__ lo) {
    int n = blockIdx.x, c = threadIdx.x;
    float v = vw[(size_t)n * 768 + 256 + c];
    __nv_bfloat16 h = __float2bfloat16(v);
    __nv_bfloat16 l = __float2bfloat16(v - __bfloat162float(h));
    hi[n * 256 + c] = h;
    lo[n * 256 + c] = l;
}

// ---------------- fused 31-layer chain on tensor cores (bf16x3) ----------------
// 32 clusters x 4 CTAs; CTA: batch b, 64-channel N slice; 256 thr = 8 warps.
// Warp tile m16 x n32. A: 64 pos-rows x 256 ch in smem (hi+lo); B per tap.
#define CROWB 528               // padded smem row bytes (132 words)
#define CBUF (64 * CROWB)       // 33792
#define CH_SMEM (4 * CBUF)      // 135168

__global__ void __launch_bounds__(256, 1) __cluster_dims__(4, 1, 1)
chain_mma(const uint4* __restrict__ xaH, const uint4* __restrict__ xaL,
          const uint4* __restrict__ gwH, const uint4* __restrict__ gwL,
          const float* __restrict__ b2, const float* __restrict__ b3,
          __nv_bfloat16* __restrict__ actH, __nv_bfloat16* __restrict__ actL) {
    extern __shared__ char sm[];
    uint32_t* AH = (uint32_t*)(sm);
    uint32_t* AL = (uint32_t*)(sm + CBUF);
    uint32_t* BH = (uint32_t*)(sm + 2 * CBUF);
    uint32_t* BL = (uint32_t*)(sm + 3 * CBUF);

    int tid = threadIdx.x;
    int warp = tid >> 5, lane = tid & 31;
    int g = lane >> 2, t = lane & 3;
    int wm = (warp & 3) * 16;
    int wn = (warp >> 2) * 32;
    int b = blockIdx.x >> 2;
    int nblk = (blockIdx.x & 3) * 64;

    const uint4* act4H = (const uint4*)actH;
    const uint4* act4L = (const uint4*)actL;

#pragma unroll 1
    for (int l = 0; l < 31; l++) {
        int taps = c_taps[l], cs = c_cs[l], tb = c_tb[l], M = c_M[l];
        int in_off = (l == 0) ? 0 : c_off[l - 1];
        int out_off = c_off[l];
        const float* bias = c_isk3[l] ? (b3 + c_bi[l] * 256) : (b2 + c_bi[l] * 256);

        // ---- load A: 64 rows x 256 ch, hi+lo ----
        if (l == 0) {
            size_t base = (size_t)b * 64 * 32;
#pragma unroll
            for (int i = 0; i < 8; i++) {
                int e = tid + 256 * i;
                int r = e >> 5, q = e & 31;
                int dst = r * CROWB + q * 16;
                *(uint4*)((char*)AH + dst) = xaH[base + (size_t)r * 32 + q];
                *(uint4*)((char*)AL + dst) = xaL[base + (size_t)r * 32 + q];
            }
        } else {
#pragma unroll
            for (int i = 0; i < 8; i++) {
                int e = tid + 256 * i;
                int r = e >> 5, q = e & 31;
                int rr = in_off + r;
                if (rr > PPAD - 1) rr = PPAD - 1;
                size_t src = ((size_t)b * PPAD + rr) * 32 + q;
                int dst = r * CROWB + q * 16;
                *(uint4*)((char*)AH + dst) = act4H[src];
                *(uint4*)((char*)AL + dst) = act4L[src];
            }
        }

        float acc[4][4];
#pragma unroll
        for (int ni = 0; ni < 4; ni++)
#pragma unroll
            for (int p = 0; p < 4; p++) acc[ni][p] = 0.f;

#pragma unroll 1
        for (int tap = 0; tap < taps; tap++) {
            __syncthreads();  // A stores done / prev-tap Bs reads done
            // ---- load B tap slice: 64 n-rows x 256 c ----
            size_t wb = (size_t)(tb + tap) * 8192 + (size_t)nblk * 32;
#pragma unroll
            for (int i = 0; i < 8; i++) {
                int e = tid + 256 * i;
                int r = e >> 5, q = e & 31;
                int dst = r * CROWB + q * 16;
                *(uint4*)((char*)BH + dst) = gwH[wb + (size_t)r * 32 + q];
                *(uint4*)((char*)BL + dst) = gwL[wb + (size_t)r * 32 + q];
            }
            __syncthreads();

            int ar0 = ((wm + g) * cs + tap) & 63;
            int ar1 = ((wm + g + 8) * cs + tap) & 63;
#pragma unroll 1
            for (int pass = 0; pass < 3; pass++) {
                const uint32_t* Aw = (pass == 2) ? AL : AH;
                const uint32_t* Bw = (pass == 1) ? BL : BH;
#pragma unroll
                for (int ks = 0; ks < 16; ks++) {
                    int kw = ks * 8 + t;
                    uint32_t af[4];
                    af[0] = Aw[ar0 * 132 + kw];
                    af[1] = Aw[ar1 * 132 + kw];
                    af[2] = Aw[ar0 * 132 + kw + 4];
                    af[3] = Aw[ar1 * 132 + kw + 4];
#pragma unroll
                    for (int ni = 0; ni < 4; ni++) {
                        int nr = wn + ni * 8 + g;
                        uint32_t bf[2];
                        bf[0] = Bw[nr * 132 + kw];
                        bf[1] = Bw[nr * 132 + kw + 4];
                        mma_bf16(acc[ni], af, bf);
                    }
                }
            }
        }

        // ---- epilogue: bias, split, store valid rows ----
        int m0g = wm + g;
#pragma unroll
        for (int ni = 0; ni < 4; ni++) {
            int n = nblk + wn + ni * 8 + 2 * t;
            float bv0 = __ldg(bias + n);
            float bv1 = __ldg(bias + n + 1);
            if (m0g < M) {
                float v0 = acc[ni][0] + bv0, v1 = acc[ni][1] + bv1;
                size_t o = ((size_t)b * PPAD + out_off + m0g) * 256 + n;
                __nv_bfloat162 hh, ll;
                hh.x = __float2bfloat16(v0);
                hh.y = __float2bfloat16(v1);
                ll.x = __float2bfloat16(v0 - __bfloat162float(hh.x));
                ll.y = __float2bfloat16(v1 - __bfloat162float(hh.y));
                *(__nv_bfloat162*)(actH + o) = hh;
                *(__nv_bfloat162*)(actL + o) = ll;
            }
            if (m0g + 8 < M) {
                float v0 = acc[ni][2] + bv0, v1 = acc[ni][3] + bv1;
                size_t o = ((size_t)b * PPAD + out_off + m0g + 8) * 256 + n;
                __nv_bfloat162 hh, ll;
                hh.x = __float2bfloat16(v0);
                hh.y = __float2bfloat16(v1);
                ll.x = __float2bfloat16(v0 - __bfloat162float(hh.x));
                ll.y = __float2bfloat16(v1 - __bfloat162float(hh.y));
                *(__nv_bfloat162*)(actH + o) = hh;
                *(__nv_bfloat162*)(actL + o) = ll;
            }
        }
        cluster_sync_all();
    }
}

// ---------------- Pc GEMM via mma.sync bf16x3 (R9 proven) ----------------
#define ROWB 528
#define ABUF (64 * ROWB)
#define SM_AH 0
#define SM_AL ABUF
#define SM_BH (2 * ABUF)
#define SM_BL (3 * ABUF)
#define PC_SMEM (4 * ABUF)

__global__ void __launch_bounds__(128, 1)
pc_mma(const uint4* __restrict__ Ahi, const uint4* __restrict__ Alo,
       const uint4* __restrict__ Bhi, const uint4* __restrict__ Blo,
       float* __restrict__ Pc) {
    extern __shared__ char sm[];
    int tid = threadIdx.x;
    int warp = tid >> 5, lane = tid & 31;
    int b = blockIdx.z, mt = blockIdx.x, nb = blockIdx.y * 64;

    {
        size_t srcb = ((size_t)b * PPAD + mt * 64) * 32;
#pragma unroll
        for (int i = 0; i < 16; i++) {
            int e = tid + 128 * i;
            int r = e >> 5, q = e & 31;
            int dst = r * ROWB + q * 16;
            *(uint4*)(sm + SM_AH + dst) = Ahi[srcb + (size_t)r * 32 + q];
            *(uint4*)(sm + SM_AL + dst) = Alo[srcb + (size_t)r * 32 + q];
        }
#pragma unroll
        for (int i = 0; i < 16; i++) {
            int e = tid + 128 * i;
            int r = e >> 5, q = e & 31;
            int dst = r * ROWB + q * 16;
            *(uint4*)(sm + SM_BH + dst) = Bhi[(size_t)(nb + r) * 32 + q];
            *(uint4*)(sm + SM_BL + dst) = Blo[(size_t)(nb + r) * 32 + q];
        }
    }
    __syncthreads();

    int g = lane >> 2, t = lane & 3;
    int wm = (warp >> 1) * 32;
    int wn = (warp & 1) * 32;

    float acc[2][4][4];
#pragma unroll
    for (int mi = 0; mi < 2; mi++)
#pragma unroll
        for (int ni = 0; ni < 4; ni++)
#pragma unroll
            for (int p = 0; p < 4; p++) acc[mi][ni][p] = 0.f;

    const uint32_t* AH = (const uint32_t*)(sm + SM_AH);
    const uint32_t* AL = (const uint32_t*)(sm + SM_AL);
    const uint32_t* BH = (const uint32_t*)(sm + SM_BH);
    const uint32_t* BL = (const uint32_t*)(sm + SM_BL);

#pragma unroll 1
    for (int pass = 0; pass < 3; pass++) {
        const uint32_t* Aw = (pass == 2) ? AL : AH;
        const uint32_t* Bw = (pass == 1) ? BL : BH;
#pragma unroll
        for (int ks = 0; ks < 16; ks++) {
            int kw = ks * 8;
            uint32_t af[2][4], bf[4][2];
#pragma unroll
            for (int mi = 0; mi < 2; mi++) {
                int row = wm + mi * 16 + g;
                af[mi][0] = Aw[row * 132 + kw + t];
                af[mi][1] = Aw[(row + 8) * 132 + kw + t];
                af[mi][2] = Aw[row * 132 + kw + t + 4];
                af[mi][3] = Aw[(row + 8) * 132 + kw + t + 4];
            }
#pragma unroll
            for (int ni = 0; ni < 4; ni++) {
                int nr = wn + ni * 8 + g;
                bf[ni][0] = Bw[nr * 132 + kw + t];
                bf[ni][1] = Bw[nr * 132 + kw + t + 4];
            }
#pragma unroll
            for (int mi = 0; mi < 2; mi++)
#pragma unroll
                for (int ni = 0; ni < 4; ni++) mma_bf16(acc[mi][ni], af[mi], bf[ni]);
        }
    }

#pragma unroll
    for (int mi = 0; mi < 2; mi++) {
        int m = mt * 64 + wm + mi * 16 + g;
#pragma unroll
        for (int ni = 0; ni < 4; ni++) {
            int n = nb + wn + ni * 8 + 2 * t;
            float* p0 = Pc + ((size_t)b * PPAD + m) * 256 + n;
            float* p1 = Pc + ((size_t)b * PPAD + m + 8) * 256 + n;
            *(float2*)p0 = make_float2(acc[mi][ni][0], acc[mi][ni][1]);
            *(float2*)p1 = make_float2(acc[mi][ni][2], acc[mi][ni][3]);
        }
    }
}

// ---------------- x-projection GEMM (fp32, proven) ----------------
__global__ void __launch_bounds__(256) proj_gemm(
    const float* __restrict__ in, int in_row_len,
    const float* __restrict__ wT, int wld,
    float* __restrict__ out, int out_ld, int M_total) {
    constexpr int KC = 32;
    constexpr int NCH = 4;
    constexpr int WGS = 2 * KC * 64 + 2 * KC * 64;

    extern __shared__ float smemf[];
    int tid = threadIdx.x;
    int wg = tid >> 7;
    int wtid = tid & 127;
    float* As = smemf + wg * WGS;
    float* Bs = As + 2 * KC * 64;
    float* Red = smemf + 2 * WGS;

    int b = blockIdx.z;
    int nblk = blockIdx.y * 64;
    int mblk = blockIdx.x * 64;
    int m0 = (wtid & 15) * 4;
    int n0 = (wtid >> 4) * 8;
    int am = wtid & 63;
    int ak0 = wtid >> 6;
    int bkb = wtid >> 4;
    int bn = (wtid & 15) * 4;

    const float* inb = in + (size_t)b * DCH * in_row_len;
    int kbase = wg * 128;

    float aA[16];
    float4 bB[4];
    auto gload = [&](int ch) {
        int c0k = kbase + ch * KC;
#pragma unroll
        for (int i = 0; i < 16; i++) {
            int k = c0k + ak0 + 2 * i;
            int mm = mblk + am;
            aA[i] = (mm < M_total) ? inb[(size_t)k * in_row_len + mm] : 0.f;
        }
#pragma unroll
        for (int i = 0; i < 4; i++) {
            int k = c0k + bkb + 8 * i;
            bB[i] = *(const float4*)&wT[(size_t)k * wld + nblk + bn];
        }
    };
    auto sts = [&](int buf) {
#pragma unroll
        for (int i = 0; i < 16; i++)
            As[buf * KC * 64 + (ak0 + 2 * i) * 64 + am] = aA[i];
#pragma unroll
        for (int i = 0; i < 4; i++)
            *(float4*)&Bs[buf * KC * 64 + (bkb + 8 * i) * 64 + bn] = bB[i];
    };

    unsigned long long acc[4][4];
#pragma unroll
    for (int mi = 0; mi < 4; mi++)
#pragma unroll
        for (int p = 0; p < 4; p++) acc[mi][p] = 0ULL;

    gload(0);
    sts(0);
    __syncthreads();

#pragma unroll 1
    for (int ch = 0; ch < NCH; ch++) {
        int buf = ch & 1;
        if (ch + 1 < NCH) gload(ch + 1);
#pragma unroll
        for (int k = 0; k < KC; k++) {
            float4 av = *(const float4*)&As[buf * KC * 64 + k * 64 + m0];
            const float* bp = &Bs[buf * KC * 64 + k * 64 + n0];
            ulonglong2 bl = *(const ulonglong2*)bp;
            ulonglong2 bh = *(const ulonglong2*)(bp + 4);
            float a[4] = {av.x, av.y, av.z, av.w};
#pragma unroll
            for (int mi = 0; mi < 4; mi++) {
                unsigned long long ad = dup2(a[mi]);
                fma2(acc[mi][0], ad, bl.x);
                fma2(acc[mi][1], ad, bl.y);
                fma2(acc[mi][2], ad, bh.x);
                fma2(acc[mi][3], ad, bh.y);
            }
        }
        if (ch + 1 < NCH) {
            sts(buf ^ 1);
            __syncthreads();
        }
    }

    float res[4][8];
#pragma unroll
    for (int mi = 0; mi < 4; mi++)
#pragma unroll
        for (int p = 0; p < 4; p++) {
            union { unsigned long long u; float2 f; } cv;
            cv.u = acc[mi][p];
            res[mi][2 * p] = cv.f.x;
            res[mi][2 * p + 1] = cv.f.y;
        }

    __syncthreads();
    if (wg == 1) {
#pragma unroll
        for (int mi = 0; mi < 4; mi++) {
            float* rp = &Red[(m0 + mi) * 64 + n0];
            *(float4*)rp = make_float4(res[mi][0], res[mi][1], res[mi][2], res[mi][3]);
            *(float4*)(rp + 4) =
                make_float4(res[mi][4], res[mi][5], res[mi][6], res[mi][7]);
        }
    }
    __syncthreads();
    if (wg != 0) return;

#pragma unroll
    for (int mi = 0; mi < 4; mi++) {
        const float* rp = &Red[(m0 + mi) * 64 + n0];
#pragma unroll
        for (int j = 0; j < 8; j++) res[mi][j] += rp[j];
    }

#pragma unroll
    for (int mi = 0; mi < 4; mi++) {
        int mm = mblk + m0 + mi;
        if (mm < M_total) {
            float* op = out + ((size_t)b * M_total + mm) * out_ld + nblk + n0;
            *(float4*)op = make_float4(res[mi][0], res[mi][1], res[mi][2], res[mi][3]);
            *(float4*)(op + 4) =
                make_float4(res[mi][4], res[mi][5], res[mi][6], res[mi][7]);
        }
    }
}

// ---------------- final output assembly ----------------
__global__ void __launch_bounds__(256) final_out(
    const float* __restrict__ P, const float* __restrict__ Pc,
    const float* __restrict__ vis_b, float* __restrict__ out) {
    int i = blockIdx.x;
    int b = blockIdx.y;
    int o = threadIdx.x;

    __shared__ int lut[64];
    if (o < 64) {
        int j = o;
        int d = j - i;
        int pg = -1;
        if (d >= 1 && d <= 15) {
            pg = c_off[d - 1] + i;
        } else if (d >= 17 && d <= 31 && ((d - 17) & 1) == 0 && (i & 1) == 0) {
            pg = c_off[15 + ((d - 17) >> 1)] + (i >> 1);
        } else if (d >= 35 && d <= 63 && ((d - 35) & 3) == 0 && (i & 3) == 0) {
            pg = c_off[23 + ((d - 35) >> 2)] + (i >> 2);
        }
        lut[j] = pg;
    }
    __syncthreads();

    float vb = __ldg(vis_b + o);
    float p1 = P[((size_t)b * NG + i) * 768 + o];
    float p2x = P[((size_t)b * NG + i) * 768 + 256 + o];
    const float* P3b = P + (size_t)b * NG * 768 + 512 + o;
    const float* Pcb = Pc + (size_t)b * PPAD * 256 + o;

    float accr[64];
#pragma unroll
    for (int j = 0; j < 64; j++) {
        float v = vb;
        if (j == i) {
            v += p1 + p2x + P3b[(size_t)j * 768];
        } else {
            int pg = lut[j];
            if (pg >= 0) v += p1 + Pcb[(size_t)pg * 256] + P3b[(size_t)j * 768];
        }
        accr[j] = v;
    }

    float4* op = (float4*)(out + (((size_t)b * DCH + o) * NG + i) * NG);
#pragma unroll
    for (int q = 0; q < 16; q++)
        op[q] = make_float4(accr[4 * q], accr[4 * q + 1], accr[4 * q + 2], accr[4 * q + 3]);
}

// ---------------- host ----------------
#define SMEM_PROJ ((2 * (2 * 32 * 64 + 2 * 32 * 64) + 64 * 64) * 4)  // 80 KB

extern "C" void kernel_launch(void* const* d_in, const int* in_sizes, int n_in,
                              void* d_out, int out_size) {
    const float* x  = (const float*)d_in[0];
    const float* w2 = (const float*)d_in[1];
    const float* b2 = (const float*)d_in[2];
    const float* w3 = (const float*)d_in[3];
    const float* b3 = (const float*)d_in[4];
    const float* vw = (const float*)d_in[5];
    const float* vb = (const float*)d_in[6];
    float* out = (float*)d_out;

    float *wP, *Pc, *P;
    uint4 *aH, *aL, *xH, *xL, *wH, *wL, *wbhi, *wblo;
    cudaGetSymbolAddress((void**)&wP, g_wP);
    cudaGetSymbolAddress((void**)&Pc, g_Pc);
    cudaGetSymbolAddress((void**)&P, g_P);
    cudaGetSymbolAddress((void**)&aH, g_act_hi);
    cudaGetSymbolAddress((void**)&aL, g_act_lo);
    cudaGetSymbolAddress((void**)&xH, g_xa_hi);
    cudaGetSymbolAddress((void**)&xL, g_xa_lo);
    cudaGetSymbolAddress((void**)&wH, g_w_hi);
    cudaGetSymbolAddress((void**)&wL, g_w_lo);
    cudaGetSymbolAddress((void**)&wbhi, g_wB_hi);
    cudaGetSymbolAddress((void**)&wblo, g_wB_lo);

    cudaFuncSetAttribute(chain_mma, cudaFuncAttributeMaxDynamicSharedMemorySize,
                         CH_SMEM);
    cudaFuncSetAttribute(proj_gemm, cudaFuncAttributeMaxDynamicSharedMemorySize,
                         SMEM_PROJ);
    cudaFuncSetAttribute(pc_mma, cudaFuncAttributeMaxDynamicSharedMemorySize, PC_SMEM);

    dim3 tb(32, 8);
    // vis_w -> wP (for fp32 x-projection)
    trans_k<<<dim3(256 / 32, 256 / 32, 3), tb>>>(vw, wP, 256, 256, 768, 768,
                                                 (size_t)256, (size_t)256);
    split_B<<<256, 256>>>(vw, (__nv_bfloat16*)wbhi, (__nv_bfloat16*)wblo);
    wsplit<<<2048, 512>>>(w2, w3, (__nv_bfloat16*)wH, (__nv_bfloat16*)wL);
    xsplit<<<dim3(2, 8, BATCH), tb>>>(x, (__nv_bfloat16*)xH, (__nv_bfloat16*)xL);

    // tensor-core chain: 32 clusters x 4 CTAs
    chain_mma<<<128, 256, CH_SMEM>>>(xH, xL, wH, wL, b2, b3,
                                     (__nv_bfloat16*)aH, (__nv_bfloat16*)aL);

    // merged x projections (fp32): [B][64][768]
    proj_gemm<<<dim3(1, 12, BATCH), 256, SMEM_PROJ>>>(x, NG, wP, 768, P, 768, NG);

    // Pc via mma.sync bf16x3 on the chain activations
    pc_mma<<<dim3(PPAD / 64, 4, BATCH), 128, PC_SMEM>>>(aH, aL, wbhi, wblo, Pc);

    final_out<<<dim3(NG, BATCH), 256>>>(P, Pc, vb, out);
}

// round 11
// speedup vs baseline: 1.6710x; 1.0759x over previous
#include <cuda_runtime.h>
#include <cuda_bf16.h>
#include <cstdint>
#include <cstddef>

#define BATCH 32
#define DCH 256
#define NG 64
#define PPAD 1088   // padded total conv positions (17 * 64)

__constant__ int c_off[31] = {0,64,128,192,252,312,372,432,488,544,600,656,708,760,812,
                              864,888,912,936,960,980,1000,1020,
                              1040,1048,1056,1064,1072,1076,1080,1084};
__constant__ int c_tb[31]  = {0,2,4,6,8,10,12,14,16,18,20,22,24,26,28, 30,
                              33,35,37,39,41,43,45, 47, 50,52,54,56,58,60,62};
__constant__ int c_taps[31] = {2,2,2,2,2,2,2,2,2,2,2,2,2,2,2, 3, 2,2,2,2,2,2,2, 3,
                               2,2,2,2,2,2,2};
__constant__ int c_cs[31]   = {1,1,1,1,1,1,1,1,1,1,1,1,1,1,1, 2, 1,1,1,1,1,1,1, 2,
                               1,1,1,1,1,1,1};
__constant__ int c_M[31]    = {63,62,61,60,59,58,57,56,55,54,53,52,51,50,49, 24,
                               23,22,21,20,19,18,17, 8, 7,6,5,4,3,2,1};
__constant__ int c_bi[31]   = {0,1,2,3,4,5,6,7,8,9,10,11,12,13,14, 0,
                               15,16,17,18,19,20,21, 1, 22,23,24,25,26,27,28};
__constant__ int c_isk3[31] = {0,0,0,0,0,0,0,0,0,0,0,0,0,0,0, 1, 0,0,0,0,0,0,0, 1,
                               0,0,0,0,0,0,0};
__constant__ int c_tb2[29]  = {0,2,4,6,8,10,12,14,16,18,20,22,24,26,28,
                               33,35,37,39,41,43,45, 50,52,54,56,58,60,62};

// ---------------- scratch ----------------
__device__ float g_wP[256 * 768];
__device__ float g_Pc[(size_t)BATCH * PPAD * DCH];
__device__ float g_P[(size_t)BATCH * NG * 768];
__device__ uint4 g_act_hi[(size_t)BATCH * PPAD * 256 / 8];
__device__ uint4 g_act_lo[(size_t)BATCH * PPAD * 256 / 8];
__device__ uint4 g_xa_hi[(size_t)BATCH * 64 * 256 / 8];
__device__ uint4 g_xa_lo[(size_t)BATCH * 64 * 256 / 8];
__device__ uint4 g_w_hi[64 * 256 * 256 / 8];
__device__ uint4 g_w_lo[64 * 256 * 256 / 8];
__device__ uint4 g_wB_hi[256 * 256 / 8];
__device__ uint4 g_wB_lo[256 * 256 / 8];

// ---------------- helpers ----------------
__device__ __forceinline__ void fma2(unsigned long long& d, unsigned long long a,
                                     unsigned long long b) {
    asm("fma.rn.f32x2 %0, %1, %2, %3;" : "=l"(d) : "l"(a), "l"(b), "l"(d));
}
__device__ __forceinline__ unsigned long long dup2(float x) {
    unsigned long long r;
    unsigned int xi = __float_as_uint(x);
    asm("mov.b64 %0, {%1, %1};" : "=l"(r) : "r"(xi));
    return r;
}
__device__ __forceinline__ void cluster_sync_all() {
    asm volatile("barrier.cluster.arrive.aligned;" ::: "memory");
    asm volatile("barrier.cluster.wait.aligned;" ::: "memory");
}
__device__ __forceinline__ uint32_t smem_u32(const void* p) {
    uint32_t a;
    asm("{ .reg .u64 t; cvta.to.shared.u64 t, %1; cvt.u32.u64 %0, t; }"
        : "=r"(a) : "l"(p));
    return a;
}
__device__ __forceinline__ void mma_bf16(float* d, const uint32_t* a,
                                         const uint32_t* b) {
    asm volatile(
        "mma.sync.aligned.m16n8k16.row.col.f32.bf16.bf16.f32 "
        "{%0,%1,%2,%3}, {%4,%5,%6,%7}, {%8,%9}, {%0,%1,%2,%3};"
        : "+f"(d[0]), "+f"(d[1]), "+f"(d[2]), "+f"(d[3])
        : "r"(a[0]), "r"(a[1]), "r"(a[2]), "r"(a[3]), "r"(b[0]), "r"(b[1]));
}
__device__ __forceinline__ void ldsm_x4(uint32_t& r0, uint32_t& r1, uint32_t& r2,
                                        uint32_t& r3, uint32_t a) {
    asm volatile("ldmatrix.sync.aligned.m8n8.x4.shared.b16 {%0,%1,%2,%3}, [%4];"
                 : "=r"(r0), "=r"(r1), "=r"(r2), "=r"(r3) : "r"(a));
}
__device__ __forceinline__ void cp16(uint32_t s, const void* g) {
    asm volatile("cp.async.cg.shared.global [%0], [%1], 16;" :: "r"(s), "l"(g)
                 : "memory");
}
#define CP_COMMIT() asm volatile("cp.async.commit_group;" ::: "memory")
#define CP_WAIT0() asm volatile("cp.async.wait_group 0;" ::: "memory")
#define CP_WAIT1() asm volatile("cp.async.wait_group 1;" ::: "memory")

// ---------------- generalized transpose (for wP) ----------------
__global__ void trans_k(const float* __restrict__ in, float* __restrict__ out,
                        int R, int C, int in_ld, int out_ld,
                        size_t in_bs, size_t out_bs) {
    __shared__ float tile[32][33];
    int bat = blockIdx.z;
    int c0 = blockIdx.x * 32, r0 = blockIdx.y * 32;
    const float* ib = in + (size_t)bat * in_bs;
    float* ob = out + (size_t)bat * out_bs;
    int tx = threadIdx.x, ty = threadIdx.y;
#pragma unroll
    for (int s = 0; s < 32; s += 8) {
        int r = r0 + ty + s, c = c0 + tx;
        if (r < R && c < C) tile[ty + s][tx] = ib[(size_t)r * in_ld + c];
    }
    __syncthreads();
#pragma unroll
    for (int s = 0; s < 32; s += 8) {
        int c = c0 + ty + s, r = r0 + tx;
        if (c < C && r < R) ob[(size_t)c * out_ld + r] = tile[tx][ty + s];
    }
}

// ---------------- x -> xact split ----------------
__global__ void xsplit(const float* __restrict__ x,
                       __nv_bfloat16* __restrict__ hi,
                       __nv_bfloat16* __restrict__ lo) {
    __shared__ float t[32][33];
    int b = blockIdx.z;
    int p0 = blockIdx.x * 32, ch0 = blockIdx.y * 32;
    int tx = threadIdx.x, ty = threadIdx.y;
#pragma unroll
    for (int s = 0; s < 32; s += 8) {
        int c = ch0 + ty + s;
        t[ty + s][tx] = x[((size_t)b * DCH + c) * NG + p0 + tx];
    }
    __syncthreads();
#pragma unroll
    for (int s = 0; s < 32; s += 8) {
        int p = p0 + ty + s, c = ch0 + tx;
        float v = t[tx][ty + s];
        __nv_bfloat16 h = __float2bfloat16(v);
        __nv_bfloat16 l = __float2bfloat16(v - __bfloat162float(h));
        size_t o = ((size_t)b * NG + p) * 256 + c;
        hi[o] = h;
        lo[o] = l;
    }
}

// ---------------- weight split ----------------
#define W2TOT (29 * 256 * 256 * 2)
#define WTOT (W2TOT + 2 * 256 * 256 * 3)
__global__ void wsplit(const float* __restrict__ w2, const float* __restrict__ w3,
                       __nv_bfloat16* __restrict__ hi,
                       __nv_bfloat16* __restrict__ lo) {
    for (int idx = blockIdx.x * blockDim.x + threadIdx.x; idx < WTOT;
         idx += gridDim.x * blockDim.x) {
        float v;
        int tap, n, c;
        if (idx < W2TOT) {
            int i2 = idx >> 17;
            int r = idx & 0x1FFFF;
            n = r >> 9;
            int r2 = r & 511;
            c = r2 >> 1;
            int kk = r2 & 1;
            v = w2[idx];
            tap = c_tb2[i2] + kk;
        } else {
            int j = idx - W2TOT;
            int i3 = j / 196608;
            int r = j % 196608;
            n = r / 768;
            int r2 = r % 768;
            c = r2 / 3;
            int kk = r2 % 3;
            v = w3[j];
            tap = (i3 ? 47 : 30) + kk;
        }
        size_t dst = (size_t)tap * 65536 + (size_t)n * 256 + c;
        __nv_bfloat16 h = __float2bfloat16(v);
        __nv_bfloat16 l = __float2bfloat16(v - __bfloat162float(h));
        hi[dst] = h;
        lo[dst] = l;
    }
}

__global__ void split_B(const float* __restrict__ vw,
                        __nv_bfloat16* __restrict__ hi,
                        __nv_bfloat16* __restrict__ lo) {
    int n = blockIdx.x, c = threadIdx.x;
    float v = vw[(size_t)n * 768 + 256 + c];
    __nv_bfloat16 h = __float2bfloat16(v);
    __nv_bfloat16 l = __float2bfloat16(v - __bfloat162float(h));
    hi[n * 256 + c] = h;
    lo[n * 256 + c] = l;
}

// ---------------- fused chain: ldmatrix + cp.async double-buffered B ----------------
#define CROWB 528
#define CBUF (64 * CROWB)       // 33792 bytes
#define CH_SMEM (6 * CBUF)      // AH | AL | BH0 | BL0 | BH1 | BL1 = 202752

__global__ void __launch_bounds__(256, 1) __cluster_dims__(4, 1, 1)
chain_mma(const uint4* __restrict__ xaH, const uint4* __restrict__ xaL,
          const uint4* __restrict__ gwH, const uint4* __restrict__ gwL,
          const float* __restrict__ b2, const float* __restrict__ b3,
          __nv_bfloat16* __restrict__ actH, __nv_bfloat16* __restrict__ actL) {
    extern __shared__ char sm[];
    uint32_t sb = smem_u32(sm);
    const uint32_t AHs = sb, ALs = sb + CBUF;
    const uint32_t BH0 = sb + 2 * CBUF, BL0 = sb + 3 * CBUF;
    const uint32_t BH1 = sb + 4 * CBUF, BL1 = sb + 5 * CBUF;

    int tid = threadIdx.x;
    int warp = tid >> 5, lane = tid & 31;
    int g = lane >> 2, t = lane & 3;
    int ridx = lane & 15, half = lane >> 4;
    int wm = (warp & 3) * 16;
    int wn = (warp >> 2) * 32;
    int b = blockIdx.x >> 2;
    int nblk = (blockIdx.x & 3) * 64;
    int lr = tid >> 5;   // load row base
    int lq = tid & 31;   // load 16B-column

    const uint4* act4H = (const uint4*)actH;
    const uint4* act4L = (const uint4*)actL;

#pragma unroll 1
    for (int l = 0; l < 31; l++) {
        int taps = c_taps[l], cs = c_cs[l], tb = c_tb[l], M = c_M[l];
        int in_off = (l == 0) ? 0 : c_off[l - 1];
        int out_off = c_off[l];
        const float* bias = c_isk3[l] ? (b3 + c_bi[l] * 256) : (b2 + c_bi[l] * 256);

        // ---- group 0: A (hi+lo) + B tap0 ----
        if (l == 0) {
            size_t base = (size_t)b * 64 * 32;
#pragma unroll
            for (int i = 0; i < 8; i++) {
                int r = lr + 8 * i;
                uint32_t dst = r * CROWB + lq * 16;
                cp16(AHs + dst, &xaH[base + (size_t)r * 32 + lq]);
                cp16(ALs + dst, &xaL[base + (size_t)r * 32 + lq]);
            }
        } else {
#pragma unroll
            for (int i = 0; i < 8; i++) {
                int r = lr + 8 * i;
                int rr = in_off + r;
                if (rr > PPAD - 1) rr = PPAD - 1;
                size_t src = ((size_t)b * PPAD + rr) * 32 + lq;
                uint32_t dst = r * CROWB + lq * 16;
                cp16(AHs + dst, &act4H[src]);
                cp16(ALs + dst, &act4L[src]);
            }
        }
        {
            size_t wb = (size_t)tb * 8192 + (size_t)nblk * 32;
#pragma unroll
            for (int i = 0; i < 8; i++) {
                int r = lr + 8 * i;
                uint32_t dst = r * CROWB + lq * 16;
                cp16(BH0 + dst, &gwH[wb + (size_t)r * 32 + lq]);
                cp16(BL0 + dst, &gwL[wb + (size_t)r * 32 + lq]);
            }
        }
        CP_COMMIT();
        // ---- group 1: B tap1 (taps is always >= 2) ----
        {
            size_t wb = (size_t)(tb + 1) * 8192 + (size_t)nblk * 32;
#pragma unroll
            for (int i = 0; i < 8; i++) {
                int r = lr + 8 * i;
                uint32_t dst = r * CROWB + lq * 16;
                cp16(BH1 + dst, &gwH[wb + (size_t)r * 32 + lq]);
                cp16(BL1 + dst, &gwL[wb + (size_t)r * 32 + lq]);
            }
        }
        CP_COMMIT();

        float acc[4][4];
#pragma unroll
        for (int ni = 0; ni < 4; ni++)
#pragma unroll
            for (int p = 0; p < 4; p++) acc[ni][p] = 0.f;

        bool active = (wm < M);
        uint32_t roff0 = (wn + ridx) * CROWB + half * 16;
        uint32_t roff1 = (wn + 16 + ridx) * CROWB + half * 16;

        auto mma_tap = [&](int tap, uint32_t BHb, uint32_t BLb) {
            int arow = ((wm + ridx) * cs + tap) & 63;
            uint32_t aHb = AHs + arow * CROWB + half * 16;
            uint32_t aLb = ALs + arow * CROWB + half * 16;
#pragma unroll 1
            for (int pass = 0; pass < 3; pass++) {
                uint32_t aB = (pass == 2) ? aLb : aHb;
                uint32_t bB = (pass == 1) ? BLb : BHb;
                uint32_t b0 = bB + roff0, b1 = bB + roff1;
#pragma unroll
                for (int ks = 0; ks < 16; ks++) {
                    uint32_t o = ks * 32;
                    uint32_t af[4];
                    ldsm_x4(af[0], af[1], af[2], af[3], aB + o);
                    uint32_t p0, p1, p2, p3, q0, q1, q2, q3;
                    ldsm_x4(p0, p1, p2, p3, b0 + o);
                    ldsm_x4(q0, q1, q2, q3, b1 + o);
                    uint32_t f0[2] = {p0, p2}, f1[2] = {p1, p3};
                    uint32_t f2[2] = {q0, q2}, f3[2] = {q1, q3};
                    mma_bf16(acc[0], af, f0);
                    mma_bf16(acc[1], af, f1);
                    mma_bf16(acc[2], af, f2);
                    mma_bf16(acc[3], af, f3);
                }
            }
        };

        CP_WAIT1();
        __syncthreads();
        if (active) mma_tap(0, BH0, BL0);

        if (taps == 3) {
            __syncthreads();  // all warps done reading buf0
            size_t wb = (size_t)(tb + 2) * 8192 + (size_t)nblk * 32;
#pragma unroll
            for (int i = 0; i < 8; i++) {
                int r = lr + 8 * i;
                uint32_t dst = r * CROWB + lq * 16;
                cp16(BH0 + dst, &gwH[wb + (size_t)r * 32 + lq]);
                cp16(BL0 + dst, &gwL[wb + (size_t)r * 32 + lq]);
            }
            CP_COMMIT();
            CP_WAIT1();
            __syncthreads();
            if (active) mma_tap(1, BH1, BL1);
            CP_WAIT0();
            __syncthreads();
            if (active) mma_tap(2, BH0, BL0);
        } else {
            CP_WAIT0();
            __syncthreads();
            if (active) mma_tap(1, BH1, BL1);
        }

        // ---- epilogue ----
        int m0g = wm + g;
#pragma unroll
        for (int ni = 0; ni < 4; ni++) {
            int n = nblk + wn + ni * 8 + 2 * t;
            float bv0 = __ldg(bias + n);
            float bv1 = __ldg(bias + n + 1);
            if (m0g < M) {
                float v0 = acc[ni][0] + bv0, v1 = acc[ni][1] + bv1;
                size_t o = ((size_t)b * PPAD + out_off + m0g) * 256 + n;
                __nv_bfloat162 hh, ll;
                hh.x = __float2bfloat16(v0);
                hh.y = __float2bfloat16(v1);
                ll.x = __float2bfloat16(v0 - __bfloat162float(hh.x));
                ll.y = __float2bfloat16(v1 - __bfloat162float(hh.y));
                *(__nv_bfloat162*)(actH + o) = hh;
                *(__nv_bfloat162*)(actL + o) = ll;
            }
            if (m0g + 8 < M) {
                float v0 = acc[ni][2] + bv0, v1 = acc[ni][3] + bv1;
                size_t o = ((size_t)b * PPAD + out_off + m0g + 8) * 256 + n;
                __nv_bfloat162 hh, ll;
                hh.x = __float2bfloat16(v0);
                hh.y = __float2bfloat16(v1);
                ll.x = __float2bfloat16(v0 - __bfloat162float(hh.x));
                ll.y = __float2bfloat16(v1 - __bfloat162float(hh.y));
                *(__nv_bfloat162*)(actH + o) = hh;
                *(__nv_bfloat162*)(actL + o) = ll;
            }
        }
        cluster_sync_all();
    }
}

// ---------------- Pc GEMM via mma.sync bf16x3 + ldmatrix ----------------
#define ROWB 528
#define ABUF (64 * ROWB)
#define SM_AH 0
#define SM_AL ABUF
#define SM_BH (2 * ABUF)
#define SM_BL (3 * ABUF)
#define PC_SMEM (4 * ABUF)

__global__ void __launch_bounds__(128, 1)
pc_mma(const uint4* __restrict__ Ahi, const uint4* __restrict__ Alo,
       const uint4* __restrict__ Bhi, const uint4* __restrict__ Blo,
       float* __restrict__ Pc) {
    extern __shared__ char sm[];
    int tid = threadIdx.x;
    int warp = tid >> 5, lane = tid & 31;
    int b = blockIdx.z, mt = blockIdx.x, nb = blockIdx.y * 64;

    {
        size_t srcb = ((size_t)b * PPAD + mt * 64) * 32;
#pragma unroll
        for (int i = 0; i < 16; i++) {
            int e = tid + 128 * i;
            int r = e >> 5, q = e & 31;
            int dst = r * ROWB + q * 16;
            *(uint4*)(sm + SM_AH + dst) = Ahi[srcb + (size_t)r * 32 + q];
            *(uint4*)(sm + SM_AL + dst) = Alo[srcb + (size_t)r * 32 + q];
        }
#pragma unroll
        for (int i = 0; i < 16; i++) {
            int e = tid + 128 * i;
            int r = e >> 5, q = e & 31;
            int dst = r * ROWB + q * 16;
            *(uint4*)(sm + SM_BH + dst) = Bhi[(size_t)(nb + r) * 32 + q];
            *(uint4*)(sm + SM_BL + dst) = Blo[(size_t)(nb + r) * 32 + q];
        }
    }
    __syncthreads();

    int g = lane >> 2, t = lane & 3;
    int ridx = lane & 15, half = lane >> 4;
    int wm = (warp >> 1) * 32;
    int wn = (warp & 1) * 32;
    uint32_t sbu = smem_u32(sm);

    uint32_t aoff0 = (wm + ridx) * ROWB + half * 16;
    uint32_t aoff1 = (wm + 16 + ridx) * ROWB + half * 16;
    uint32_t boff0 = (wn + ridx) * ROWB + half * 16;
    uint32_t boff1 = (wn + 16 + ridx) * ROWB + half * 16;

    float acc[2][4][4];
#pragma unroll
    for (int mi = 0; mi < 2; mi++)
#pragma unroll
        for (int ni = 0; ni < 4; ni++)
#pragma unroll
            for (int p = 0; p < 4; p++) acc[mi][ni][p] = 0.f;

#pragma unroll 1
    for (int pass = 0; pass < 3; pass++) {
        uint32_t Ab = sbu + ((pass == 2) ? SM_AL : SM_AH);
        uint32_t Bb = sbu + ((pass == 1) ? SM_BL : SM_BH);
#pragma unroll
        for (int ks = 0; ks < 16; ks++) {
            uint32_t o = ks * 32;
            uint32_t a0[4], a1[4];
            ldsm_x4(a0[0], a0[1], a0[2], a0[3], Ab + aoff0 + o);
            ldsm_x4(a1[0], a1[1], a1[2], a1[3], Ab + aoff1 + o);
            uint32_t p0, p1, p2, p3, q0, q1, q2, q3;
            ldsm_x4(p0, p1, p2, p3, Bb + boff0 + o);
            ldsm_x4(q0, q1, q2, q3, Bb + boff1 + o);
            uint32_t f0[2] = {p0, p2}, f1[2] = {p1, p3};
            uint32_t f2[2] = {q0, q2}, f3[2] = {q1, q3};
            mma_bf16(acc[0][0], a0, f0);
            mma_bf16(acc[0][1], a0, f1);
            mma_bf16(acc[0][2], a0, f2);
            mma_bf16(acc[0][3], a0, f3);
            mma_bf16(acc[1][0], a1, f0);
            mma_bf16(acc[1][1], a1, f1);
            mma_bf16(acc[1][2], a1, f2);
            mma_bf16(acc[1][3], a1, f3);
        }
    }

#pragma unroll
    for (int mi = 0; mi < 2; mi++) {
        int m = mt * 64 + wm + mi * 16 + g;
#pragma unroll
        for (int ni = 0; ni < 4; ni++) {
            int n = nb + wn + ni * 8 + 2 * t;
            float* p0 = Pc + ((size_t)b * PPAD + m) * 256 + n;
            float* p1 = Pc + ((size_t)b * PPAD + m + 8) * 256 + n;
            *(float2*)p0 = make_float2(acc[mi][ni][0], acc[mi][ni][1]);
            *(float2*)p1 = make_float2(acc[mi][ni][2], acc[mi][ni][3]);
        }
    }
}

// ---------------- x-projection GEMM (fp32, proven) ----------------
__global__ void __launch_bounds__(256) proj_gemm(
    const float* __restrict__ in, int in_row_len,
    const float* __restrict__ wT, int wld,
    float* __restrict__ out, int out_ld, int M_total) {
    constexpr int KC = 32;
    constexpr int NCH = 4;
    constexpr int WGS = 2 * KC * 64 + 2 * KC * 64;

    extern __shared__ float smemf[];
    int tid = threadIdx.x;
    int wg = tid >> 7;
    int wtid = tid & 127;
    float* As = smemf + wg * WGS;
    float* Bs = As + 2 * KC * 64;
    float* Red = smemf + 2 * WGS;

    int b = blockIdx.z;
    int nblk = blockIdx.y * 64;
    int mblk = blockIdx.x * 64;
    int m0 = (wtid & 15) * 4;
    int n0 = (wtid >> 4) * 8;
    int am = wtid & 63;
    int ak0 = wtid >> 6;
    int bkb = wtid >> 4;
    int bn = (wtid & 15) * 4;

    const float* inb = in + (size_t)b * DCH * in_row_len;
    int kbase = wg * 128;

    float aA[16];
    float4 bB[4];
    auto gload = [&](int ch) {
        int c0k = kbase + ch * KC;
#pragma unroll
        for (int i = 0; i < 16; i++) {
            int k = c0k + ak0 + 2 * i;
            int mm = mblk + am;
            aA[i] = (mm < M_total) ? inb[(size_t)k * in_row_len + mm] : 0.f;
        }
#pragma unroll
        for (int i = 0; i < 4; i++) {
            int k = c0k + bkb + 8 * i;
            bB[i] = *(const float4*)&wT[(size_t)k * wld + nblk + bn];
        }
    };
    auto sts = [&](int buf) {
#pragma unroll
        for (int i = 0; i < 16; i++)
            As[buf * KC * 64 + (ak0 + 2 * i) * 64 + am] = aA[i];
#pragma unroll
        for (int i = 0; i < 4; i++)
            *(float4*)&Bs[buf * KC * 64 + (bkb + 8 * i) * 64 + bn] = bB[i];
    };

    unsigned long long acc[4][4];
#pragma unroll
    for (int mi = 0; mi < 4; mi++)
#pragma unroll
        for (int p = 0; p < 4; p++) acc[mi][p] = 0ULL;

    gload(0);
    sts(0);
    __syncthreads();

#pragma unroll 1
    for (int ch = 0; ch < NCH; ch++) {
        int buf = ch & 1;
        if (ch + 1 < NCH) gload(ch + 1);
#pragma unroll
        for (int k = 0; k < KC; k++) {
            float4 av = *(const float4*)&As[buf * KC * 64 + k * 64 + m0];
            const float* bp = &Bs[buf * KC * 64 + k * 64 + n0];
            ulonglong2 bl = *(const ulonglong2*)bp;
            ulonglong2 bh = *(const ulonglong2*)(bp + 4);
            float a[4] = {av.x, av.y, av.z, av.w};
#pragma unroll
            for (int mi = 0; mi < 4; mi++) {
                unsigned long long ad = dup2(a[mi]);
                fma2(acc[mi][0], ad, bl.x);
                fma2(acc[mi][1], ad, bl.y);
                fma2(acc[mi][2], ad, bh.x);
                fma2(acc[mi][3], ad, bh.y);
            }
        }
        if (ch + 1 < NCH) {
            sts(buf ^ 1);
            __syncthreads();
        }
    }

    float res[4][8];
#pragma unroll
    for (int mi = 0; mi < 4; mi++)
#pragma unroll
        for (int p = 0; p < 4; p++) {
            union { unsigned long long u; float2 f; } cv;
            cv.u = acc[mi][p];
            res[mi][2 * p] = cv.f.x;
            res[mi][2 * p + 1] = cv.f.y;
        }

    __syncthreads();
    if (wg == 1) {
#pragma unroll
        for (int mi = 0; mi < 4; mi++) {
            float* rp = &Red[(m0 + mi) * 64 + n0];
            *(float4*)rp = make_float4(res[mi][0], res[mi][1], res[mi][2], res[mi][3]);
            *(float4*)(rp + 4) =
                make_float4(res[mi][4], res[mi][5], res[mi][6], res[mi][7]);
        }
    }
    __syncthreads();
    if (wg != 0) return;

#pragma unroll
    for (int mi = 0; mi < 4; mi++) {
        const float* rp = &Red[(m0 + mi) * 64 + n0];
#pragma unroll
        for (int j = 0; j < 8; j++) res[mi][j] += rp[j];
    }

#pragma unroll
    for (int mi = 0; mi < 4; mi++) {
        int mm = mblk + m0 + mi;
        if (mm < M_total) {
            float* op = out + ((size_t)b * M_total + mm) * out_ld + nblk + n0;
            *(float4*)op = make_float4(res[mi][0], res[mi][1], res[mi][2], res[mi][3]);
            *(float4*)(op + 4) =
                make_float4(res[mi][4], res[mi][5], res[mi][6], res[mi][7]);
        }
    }
}

// ---------------- final output assembly ----------------
__global__ void __launch_bounds__(256) final_out(
    const float* __restrict__ P, const float* __restrict__ Pc,
    const float* __restrict__ vis_b, float* __restrict__ out) {
    int i = blockIdx.x;
    int b = blockIdx.y;
    int o = threadIdx.x;

    __shared__ int lut[64];
    if (o < 64) {
        int j = o;
        int d = j - i;
        int pg = -1;
        if (d >= 1 && d <= 15) {
            pg = c_off[d - 1] + i;
        } else if (d >= 17 && d <= 31 && ((d - 17) & 1) == 0 && (i & 1) == 0) {
            pg = c_off[15 + ((d - 17) >> 1)] + (i >> 1);
        } else if (d >= 35 && d <= 63 && ((d - 35) & 3) == 0 && (i & 3) == 0) {
            pg = c_off[23 + ((d - 35) >> 2)] + (i >> 2);
        }
        lut[j] = pg;
    }
    __syncthreads();

    float vb = __ldg(vis_b + o);
    float p1 = P[((size_t)b * NG + i) * 768 + o];
    float p2x = P[((size_t)b * NG + i) * 768 + 256 + o];
    const float* P3b = P + (size_t)b * NG * 768 + 512 + o;
    const float* Pcb = Pc + (size_t)b * PPAD * 256 + o;

    float accr[64];
#pragma unroll
    for (int j = 0; j < 64; j++) {
        float v = vb;
        if (j == i) {
            v += p1 + p2x + P3b[(size_t)j * 768];
        } else {
            int pg = lut[j];
            if (pg >= 0) v += p1 + Pcb[(size_t)pg * 256] + P3b[(size_t)j * 768];
        }
        accr[j] = v;
    }

    float4* op = (float4*)(out + (((size_t)b * DCH + o) * NG + i) * NG);
#pragma unroll
    for (int q = 0; q < 16; q++)
        op[q] = make_float4(accr[4 * q], accr[4 * q + 1], accr[4 * q + 2], accr[4 * q + 3]);
}

// ---------------- host ----------------
#define SMEM_PROJ ((2 * (2 * 32 * 64 + 2 * 32 * 64) + 64 * 64) * 4)  // 80 KB

extern "C" void kernel_launch(void* const* d_in, const int* in_sizes, int n_in,
                              void* d_out, int out_size) {
    const float* x  = (const float*)d_in[0];
    const float* w2 = (const float*)d_in[1];
    const float* b2 = (const float*)d_in[2];
    const float* w3 = (const float*)d_in[3];
    const float* b3 = (const float*)d_in[4];
    const float* vw = (const float*)d_in[5];
    const float* vb = (const float*)d_in[6];
    float* out = (float*)d_out;

    float *wP, *Pc, *P;
    uint4 *aH, *aL, *xH, *xL, *wH, *wL, *wbhi, *wblo;
    cudaGetSymbolAddress((void**)&wP, g_wP);
    cudaGetSymbolAddress((void**)&Pc, g_Pc);
    cudaGetSymbolAddress((void**)&P, g_P);
    cudaGetSymbolAddress((void**)&aH, g_act_hi);
    cudaGetSymbolAddress((void**)&aL, g_act_lo);
    cudaGetSymbolAddress((void**)&xH, g_xa_hi);
    cudaGetSymbolAddress((void**)&xL, g_xa_lo);
    cudaGetSymbolAddress((void**)&wH, g_w_hi);
    cudaGetSymbolAddress((void**)&wL, g_w_lo);
    cudaGetSymbolAddress((void**)&wbhi, g_wB_hi);
    cudaGetSymbolAddress((void**)&wblo, g_wB_lo);

    cudaFuncSetAttribute(chain_mma, cudaFuncAttributeMaxDynamicSharedMemorySize,
                         CH_SMEM);
    cudaFuncSetAttribute(proj_gemm, cudaFuncAttributeMaxDynamicSharedMemorySize,
                         SMEM_PROJ);
    cudaFuncSetAttribute(pc_mma, cudaFuncAttributeMaxDynamicSharedMemorySize, PC_SMEM);

    dim3 tb(32, 8);
    trans_k<<<dim3(256 / 32, 256 / 32, 3), tb>>>(vw, wP, 256, 256, 768, 768,
                                                 (size_t)256, (size_t)256);
    split_B<<<256, 256>>>(vw, (__nv_bfloat16*)wbhi, (__nv_bfloat16*)wblo);
    wsplit<<<2048, 512>>>(w2, w3, (__nv_bfloat16*)wH, (__nv_bfloat16*)wL);
    xsplit<<<dim3(2, 8, BATCH), tb>>>(x, (__nv_bfloat16*)xH, (__nv_bfloat16*)xL);

    // tensor-core chain: 32 clusters x 4 CTAs
    chain_mma<<<128, 256, CH_SMEM>>>(xH, xL, wH, wL, b2, b3,
                                     (__nv_bfloat16*)aH, (__nv_bfloat16*)aL);

    // merged x projections (fp32): [B][64][768]
    proj_gemm<<<dim3(1, 12, BATCH), 256, SMEM_PROJ>>>(x, NG, wP, 768, P, 768, NG);

    // Pc via mma.sync bf16x3 on the chain activations
    pc_mma<<<dim3(PPAD / 64, 4, BATCH), 128, PC_SMEM>>>(aH, aL, wbhi, wblo, Pc);

    final_out<<<dim3(NG, BATCH), 256>>>(P, Pc, vb, out);
}

// round 12
// speedup vs baseline: 1.7167x; 1.0273x over previous
#include <cuda_runtime.h>
#include <cuda_bf16.h>
#include <cstdint>
#include <cstddef>

#define BATCH 32
#define DCH 256
#define NG 64
#define PPAD 1088   // padded total conv positions (17 * 64)

__constant__ int c_off[31] = {0,64,128,192,252,312,372,432,488,544,600,656,708,760,812,
                              864,888,912,936,960,980,1000,1020,
                              1040,1048,1056,1064,1072,1076,1080,1084};
__constant__ int c_tb[31]  = {0,2,4,6,8,10,12,14,16,18,20,22,24,26,28, 30,
                              33,35,37,39,41,43,45, 47, 50,52,54,56,58,60,62};
__constant__ int c_taps[31] = {2,2,2,2,2,2,2,2,2,2,2,2,2,2,2, 3, 2,2,2,2,2,2,2, 3,
                               2,2,2,2,2,2,2};
__constant__ int c_cs[31]   = {1,1,1,1,1,1,1,1,1,1,1,1,1,1,1, 2, 1,1,1,1,1,1,1, 2,
                               1,1,1,1,1,1,1};
__constant__ int c_M[31]    = {63,62,61,60,59,58,57,56,55,54,53,52,51,50,49, 24,
                               23,22,21,20,19,18,17, 8, 7,6,5,4,3,2,1};
__constant__ int c_bi[31]   = {0,1,2,3,4,5,6,7,8,9,10,11,12,13,14, 0,
                               15,16,17,18,19,20,21, 1, 22,23,24,25,26,27,28};
__constant__ int c_isk3[31] = {0,0,0,0,0,0,0,0,0,0,0,0,0,0,0, 1, 0,0,0,0,0,0,0, 1,
                               0,0,0,0,0,0,0};
__constant__ int c_tb2[29]  = {0,2,4,6,8,10,12,14,16,18,20,22,24,26,28,
                               33,35,37,39,41,43,45, 50,52,54,56,58,60,62};

// ---------------- scratch ----------------
__device__ float g_Pc[(size_t)BATCH * PPAD * DCH];
__device__ float g_P[(size_t)BATCH * NG * 768];
__device__ uint4 g_act_hi[(size_t)BATCH * PPAD * 256 / 8];
__device__ uint4 g_act_lo[(size_t)BATCH * PPAD * 256 / 8];
__device__ uint4 g_xa_hi[(size_t)BATCH * 64 * 256 / 8];
__device__ uint4 g_xa_lo[(size_t)BATCH * 64 * 256 / 8];
__device__ uint4 g_w_hi[64 * 256 * 256 / 8];
__device__ uint4 g_w_lo[64 * 256 * 256 / 8];
// full vis_w split: rows r = s*256+o, cols c: vw[o][s*256+c]
__device__ uint4 g_wB_hi[768 * 256 / 8];
__device__ uint4 g_wB_lo[768 * 256 / 8];

// ---------------- helpers ----------------
__device__ __forceinline__ void cluster_sync_all() {
    asm volatile("barrier.cluster.arrive.aligned;" ::: "memory");
    asm volatile("barrier.cluster.wait.aligned;" ::: "memory");
}
__device__ __forceinline__ uint32_t smem_u32(const void* p) {
    uint32_t a;
    asm("{ .reg .u64 t; cvta.to.shared.u64 t, %1; cvt.u32.u64 %0, t; }"
        : "=r"(a) : "l"(p));
    return a;
}
__device__ __forceinline__ void mma_bf16(float* d, const uint32_t* a,
                                         const uint32_t* b) {
    asm volatile(
        "mma.sync.aligned.m16n8k16.row.col.f32.bf16.bf16.f32 "
        "{%0,%1,%2,%3}, {%4,%5,%6,%7}, {%8,%9}, {%0,%1,%2,%3};"
        : "+f"(d[0]), "+f"(d[1]), "+f"(d[2]), "+f"(d[3])
        : "r"(a[0]), "r"(a[1]), "r"(a[2]), "r"(a[3]), "r"(b[0]), "r"(b[1]));
}
__device__ __forceinline__ void ldsm_x4(uint32_t& r0, uint32_t& r1, uint32_t& r2,
                                        uint32_t& r3, uint32_t a) {
    asm volatile("ldmatrix.sync.aligned.m8n8.x4.shared.b16 {%0,%1,%2,%3}, [%4];"
                 : "=r"(r0), "=r"(r1), "=r"(r2), "=r"(r3) : "r"(a));
}
__device__ __forceinline__ void cp16(uint32_t s, const void* g) {
    asm volatile("cp.async.cg.shared.global [%0], [%1], 16;" :: "r"(s), "l"(g)
                 : "memory");
}
#define CP_COMMIT() asm volatile("cp.async.commit_group;" ::: "memory")
#define CP_WAIT0() asm volatile("cp.async.wait_group 0;" ::: "memory")

// ---------------- x -> xact split ----------------
__global__ void xsplit(const float* __restrict__ x,
                       __nv_bfloat16* __restrict__ hi,
                       __nv_bfloat16* __restrict__ lo) {
    __shared__ float t[32][33];
    int b = blockIdx.z;
    int p0 = blockIdx.x * 32, ch0 = blockIdx.y * 32;
    int tx = threadIdx.x, ty = threadIdx.y;
#pragma unroll
    for (int s = 0; s < 32; s += 8) {
        int c = ch0 + ty + s;
        t[ty + s][tx] = x[((size_t)b * DCH + c) * NG + p0 + tx];
    }
    __syncthreads();
#pragma unroll
    for (int s = 0; s < 32; s += 8) {
        int p = p0 + ty + s, c = ch0 + tx;
        float v = t[tx][ty + s];
        __nv_bfloat16 h = __float2bfloat16(v);
        __nv_bfloat16 l = __float2bfloat16(v - __bfloat162float(h));
        size_t o = ((size_t)b * NG + p) * 256 + c;
        hi[o] = h;
        lo[o] = l;
    }
}

// ---------------- weight split ----------------
#define W2TOT (29 * 256 * 256 * 2)
#define WTOT (W2TOT + 2 * 256 * 256 * 3)
__global__ void wsplit(const float* __restrict__ w2, const float* __restrict__ w3,
                       __nv_bfloat16* __restrict__ hi,
                       __nv_bfloat16* __restrict__ lo) {
    for (int idx = blockIdx.x * blockDim.x + threadIdx.x; idx < WTOT;
         idx += gridDim.x * blockDim.x) {
        float v;
        int tap, n, c;
        if (idx < W2TOT) {
            int i2 = idx >> 17;
            int r = idx & 0x1FFFF;
            n = r >> 9;
            int r2 = r & 511;
            c = r2 >> 1;
            int kk = r2 & 1;
            v = w2[idx];
            tap = c_tb2[i2] + kk;
        } else {
            int j = idx - W2TOT;
            int i3 = j / 196608;
            int r = j % 196608;
            n = r / 768;
            int r2 = r % 768;
            c = r2 / 3;
            int kk = r2 % 3;
            v = w3[j];
            tap = (i3 ? 47 : 30) + kk;
        }
        size_t dst = (size_t)tap * 65536 + (size_t)n * 256 + c;
        __nv_bfloat16 h = __float2bfloat16(v);
        __nv_bfloat16 l = __float2bfloat16(v - __bfloat162float(h));
        hi[dst] = h;
        lo[dst] = l;
    }
}

// split full vis_w: row r = s*256+o  ->  B[r][c] = vw[o][s*256+c]
__global__ void split_B(const float* __restrict__ vw,
                        __nv_bfloat16* __restrict__ hi,
                        __nv_bfloat16* __restrict__ lo) {
    int r = blockIdx.x, c = threadIdx.x;
    int o = r & 255, s = r >> 8;
    float v = vw[(size_t)o * 768 + s * 256 + c];
    __nv_bfloat16 h = __float2bfloat16(v);
    __nv_bfloat16 l = __float2bfloat16(v - __bfloat162float(h));
    hi[(size_t)r * 256 + c] = h;
    lo[(size_t)r * 256 + c] = l;
}

// ---------------- fused chain: merged-pass mma + cross-layer B prefetch ----------------
#define CROWB 528
#define CBUF (64 * CROWB)       // 33792 bytes
#define CH_SMEM (6 * CBUF)      // AH | AL | BH0 | BL0 | BH1 | BL1

__global__ void __launch_bounds__(256, 1) __cluster_dims__(4, 1, 1)
chain_mma(const uint4* __restrict__ xaH, const uint4* __restrict__ xaL,
          const uint4* __restrict__ gwH, const uint4* __restrict__ gwL,
          const float* __restrict__ b2, const float* __restrict__ b3,
          __nv_bfloat16* __restrict__ actH, __nv_bfloat16* __restrict__ actL) {
    extern __shared__ char sm[];
    uint32_t sb = smem_u32(sm);
    const uint32_t AHs = sb, ALs = sb + CBUF;
    const uint32_t BH0 = sb + 2 * CBUF, BL0 = sb + 3 * CBUF;
    const uint32_t BH1 = sb + 4 * CBUF, BL1 = sb + 5 * CBUF;

    int tid = threadIdx.x;
    int warp = tid >> 5, lane = tid & 31;
    int g = lane >> 2, t = lane & 3;
    int ridx = lane & 15, half = lane >> 4;
    int wm = (warp & 3) * 16;
    int wn = (warp >> 2) * 32;
    int b = blockIdx.x >> 2;
    int nblk = (blockIdx.x & 3) * 64;
    int lr = tid >> 5;
    int lq = tid & 31;

    const uint4* act4H = (const uint4*)actH;
    const uint4* act4L = (const uint4*)actL;

    uint32_t roff0 = (wn + ridx) * CROWB + half * 16;
    uint32_t roff1 = (wn + 16 + ridx) * CROWB + half * 16;

    auto load_B = [&](int tap, uint32_t BHb, uint32_t BLb) {
        size_t wb = (size_t)tap * 8192 + (size_t)nblk * 32;
#pragma unroll
        for (int i = 0; i < 8; i++) {
            int r = lr + 8 * i;
            uint32_t dst = r * CROWB + lq * 16;
            cp16(BHb + dst, &gwH[wb + (size_t)r * 32 + lq]);
            cp16(BLb + dst, &gwL[wb + (size_t)r * 32 + lq]);
        }
    };

    // preload layer-0 weights
    load_B(0, BH0, BL0);
    load_B(1, BH1, BL1);
    CP_COMMIT();

#pragma unroll 1
    for (int l = 0; l < 31; l++) {
        int taps = c_taps[l], cs = c_cs[l], tb = c_tb[l], M = c_M[l];
        int in_off = (l == 0) ? 0 : c_off[l - 1];
        int out_off = c_off[l];
        const float* bias = c_isk3[l] ? (b3 + c_bi[l] * 256) : (b2 + c_bi[l] * 256);

        // A load (depends on previous layer via the cluster_sync at loop end)
        if (l == 0) {
            size_t base = (size_t)b * 64 * 32;
#pragma unroll
            for (int i = 0; i < 8; i++) {
                int r = lr + 8 * i;
                uint32_t dst = r * CROWB + lq * 16;
                cp16(AHs + dst, &xaH[base + (size_t)r * 32 + lq]);
                cp16(ALs + dst, &xaL[base + (size_t)r * 32 + lq]);
            }
        } else {
#pragma unroll
            for (int i = 0; i < 8; i++) {
                int r = lr + 8 * i;
                int rr = in_off + r;
                if (rr > PPAD - 1) rr = PPAD - 1;
                size_t src = ((size_t)b * PPAD + rr) * 32 + lq;
                uint32_t dst = r * CROWB + lq * 16;
                cp16(AHs + dst, &act4H[src]);
                cp16(ALs + dst, &act4L[src]);
            }
        }
        CP_COMMIT();

        float acc[4][4];
#pragma unroll
        for (int ni = 0; ni < 4; ni++)
#pragma unroll
            for (int p = 0; p < 4; p++) acc[ni][p] = 0.f;

        bool active = (wm < M);

        auto mma_tap = [&](int tap, uint32_t BHb, uint32_t BLb) {
            int arow = ((wm + ridx) * cs + tap) & 63;
            uint32_t aHb = AHs + arow * CROWB + half * 16;
            uint32_t aLb = ALs + arow * CROWB + half * 16;
            uint32_t bh0 = BHb + roff0, bh1 = BHb + roff1;
            uint32_t bl0 = BLb + roff0, bl1 = BLb + roff1;
#pragma unroll
            for (int ks = 0; ks < 16; ks++) {
                uint32_t o = ks * 32;
                uint32_t ah[4], al[4];
                ldsm_x4(ah[0], ah[1], ah[2], ah[3], aHb + o);
                ldsm_x4(al[0], al[1], al[2], al[3], aLb + o);
                uint32_t p0, p1, p2, p3, q0, q1, q2, q3;
                ldsm_x4(p0, p1, p2, p3, bh0 + o);
                ldsm_x4(q0, q1, q2, q3, bh1 + o);
                uint32_t r0, r1, r2, r3, s0, s1, s2, s3;
                ldsm_x4(r0, r1, r2, r3, bl0 + o);
                ldsm_x4(s0, s1, s2, s3, bl1 + o);
                uint32_t fh0[2] = {p0, p2}, fh1[2] = {p1, p3};
                uint32_t fh2[2] = {q0, q2}, fh3[2] = {q1, q3};
                uint32_t fl0[2] = {r0, r2}, fl1[2] = {r1, r3};
                uint32_t fl2[2] = {s0, s2}, fl3[2] = {s1, s3};
                mma_bf16(acc[0], ah, fh0);
                mma_bf16(acc[1], ah, fh1);
                mma_bf16(acc[2], ah, fh2);
                mma_bf16(acc[3], ah, fh3);
                mma_bf16(acc[0], al, fh0);
                mma_bf16(acc[1], al, fh1);
                mma_bf16(acc[2], al, fh2);
                mma_bf16(acc[3], al, fh3);
                mma_bf16(acc[0], ah, fl0);
                mma_bf16(acc[1], ah, fl1);
                mma_bf16(acc[2], ah, fl2);
                mma_bf16(acc[3], ah, fl3);
            }
        };

        CP_WAIT0();
        __syncthreads();
        if (active) mma_tap(0, BH0, BL0);

        if (taps == 3) {
            __syncthreads();  // everyone done with buf0
            load_B(tb + 2, BH0, BL0);
            CP_COMMIT();
            if (active) mma_tap(1, BH1, BL1);
            CP_WAIT0();
            __syncthreads();
            if (active) mma_tap(2, BH0, BL0);
        } else {
            if (active) mma_tap(1, BH1, BL1);
        }

        __syncthreads();  // all B reads done -> buffers free
        if (l < 30) {     // prefetch next layer's weights (independent of sync)
            load_B(c_tb[l + 1], BH0, BL0);
            load_B(c_tb[l + 1] + 1, BH1, BL1);
            CP_COMMIT();
        }

        // epilogue
        int m0g = wm + g;
#pragma unroll
        for (int ni = 0; ni < 4; ni++) {
            int n = nblk + wn + ni * 8 + 2 * t;
            float bv0 = __ldg(bias + n);
            float bv1 = __ldg(bias + n + 1);
            if (m0g < M) {
                float v0 = acc[ni][0] + bv0, v1 = acc[ni][1] + bv1;
                size_t o = ((size_t)b * PPAD + out_off + m0g) * 256 + n;
                __nv_bfloat162 hh, ll;
                hh.x = __float2bfloat16(v0);
                hh.y = __float2bfloat16(v1);
                ll.x = __float2bfloat16(v0 - __bfloat162float(hh.x));
                ll.y = __float2bfloat16(v1 - __bfloat162float(hh.y));
                *(__nv_bfloat162*)(actH + o) = hh;
                *(__nv_bfloat162*)(actL + o) = ll;
            }
            if (m0g + 8 < M) {
                float v0 = acc[ni][2] + bv0, v1 = acc[ni][3] + bv1;
                size_t o = ((size_t)b * PPAD + out_off + m0g + 8) * 256 + n;
                __nv_bfloat162 hh, ll;
                hh.x = __float2bfloat16(v0);
                hh.y = __float2bfloat16(v1);
                ll.x = __float2bfloat16(v0 - __bfloat162float(hh.x));
                ll.y = __float2bfloat16(v1 - __bfloat162float(hh.y));
                *(__nv_bfloat162*)(actH + o) = hh;
                *(__nv_bfloat162*)(actL + o) = ll;
            }
        }
        cluster_sync_all();
    }
}

// ---------------- generic GEMM via mma.sync bf16x3 + ldmatrix ----------------
// out[b, m, nb+n] = sum_c A[b,m,c] * B[nb+n,c]
// grid: (a_rows/64, N/64, BATCH); A: [B][a_rows][256] bf16 hi/lo; B: [N][256]
#define ROWB 528
#define ABUF (64 * ROWB)
#define SM_AH 0
#define SM_AL ABUF
#define SM_BH (2 * ABUF)
#define SM_BL (3 * ABUF)
#define PC_SMEM (4 * ABUF)

__global__ void __launch_bounds__(128, 1)
gemm_mma(const uint4* __restrict__ Ahi, const uint4* __restrict__ Alo,
         const uint4* __restrict__ Bhi, const uint4* __restrict__ Blo,
         float* __restrict__ out, int a_rows, int out_ld) {
    extern __shared__ char sm[];
    int tid = threadIdx.x;
    int warp = tid >> 5, lane = tid & 31;
    int b = blockIdx.z, mt = blockIdx.x, nb = blockIdx.y * 64;

    {
        size_t srcb = ((size_t)b * a_rows + mt * 64) * 32;
#pragma unroll
        for (int i = 0; i < 16; i++) {
            int e = tid + 128 * i;
            int r = e >> 5, q = e & 31;
            int dst = r * ROWB + q * 16;
            *(uint4*)(sm + SM_AH + dst) = Ahi[srcb + (size_t)r * 32 + q];
            *(uint4*)(sm + SM_AL + dst) = Alo[srcb + (size_t)r * 32 + q];
        }
#pragma unroll
        for (int i = 0; i < 16; i++) {
            int e = tid + 128 * i;
            int r = e >> 5, q = e & 31;
            int dst = r * ROWB + q * 16;
            *(uint4*)(sm + SM_BH + dst) = Bhi[(size_t)(nb + r) * 32 + q];
            *(uint4*)(sm + SM_BL + dst) = Blo[(size_t)(nb + r) * 32 + q];
        }
    }
    __syncthreads();

    int g = lane >> 2, t = lane & 3;
    int ridx = lane & 15, half = lane >> 4;
    int wm = (warp >> 1) * 32;
    int wn = (warp & 1) * 32;
    uint32_t sbu = smem_u32(sm);

    uint32_t aoff0 = (wm + ridx) * ROWB + half * 16;
    uint32_t aoff1 = (wm + 16 + ridx) * ROWB + half * 16;
    uint32_t boff0 = (wn + ridx) * ROWB + half * 16;
    uint32_t boff1 = (wn + 16 + ridx) * ROWB + half * 16;

    float acc[2][4][4];
#pragma unroll
    for (int mi = 0; mi < 2; mi++)
#pragma unroll
        for (int ni = 0; ni < 4; ni++)
#pragma unroll
            for (int p = 0; p < 4; p++) acc[mi][ni][p] = 0.f;

#pragma unroll 1
    for (int pass = 0; pass < 3; pass++) {
        uint32_t Ab = sbu + ((pass == 2) ? SM_AL : SM_AH);
        uint32_t Bb = sbu + ((pass == 1) ? SM_BL : SM_BH);
#pragma unroll
        for (int ks = 0; ks < 16; ks++) {
            uint32_t o = ks * 32;
            uint32_t a0[4], a1[4];
            ldsm_x4(a0[0], a0[1], a0[2], a0[3], Ab + aoff0 + o);
            ldsm_x4(a1[0], a1[1], a1[2], a1[3], Ab + aoff1 + o);
            uint32_t p0, p1, p2, p3, q0, q1, q2, q3;
            ldsm_x4(p0, p1, p2, p3, Bb + boff0 + o);
            ldsm_x4(q0, q1, q2, q3, Bb + boff1 + o);
            uint32_t f0[2] = {p0, p2}, f1[2] = {p1, p3};
            uint32_t f2[2] = {q0, q2}, f3[2] = {q1, q3};
            mma_bf16(acc[0][0], a0, f0);
            mma_bf16(acc[0][1], a0, f1);
            mma_bf16(acc[0][2], a0, f2);
            mma_bf16(acc[0][3], a0, f3);
            mma_bf16(acc[1][0], a1, f0);
            mma_bf16(acc[1][1], a1, f1);
            mma_bf16(acc[1][2], a1, f2);
            mma_bf16(acc[1][3], a1, f3);
        }
    }

#pragma unroll
    for (int mi = 0; mi < 2; mi++) {
        int m = mt * 64 + wm + mi * 16 + g;
#pragma unroll
        for (int ni = 0; ni < 4; ni++) {
            int n = nb + wn + ni * 8 + 2 * t;
            float* p0 = out + ((size_t)b * a_rows + m) * out_ld + n;
            float* p1 = out + ((size_t)b * a_rows + m + 8) * out_ld + n;
            *(float2*)p0 = make_float2(acc[mi][ni][0], acc[mi][ni][1]);
            *(float2*)p1 = make_float2(acc[mi][ni][2], acc[mi][ni][3]);
        }
    }
}

// ---------------- final output assembly ----------------
__global__ void __launch_bounds__(256) final_out(
    const float* __restrict__ P, const float* __restrict__ Pc,
    const float* __restrict__ vis_b, float* __restrict__ out) {
    int i = blockIdx.x;
    int b = blockIdx.y;
    int o = threadIdx.x;

    __shared__ int lut[64];
    if (o < 64) {
        int j = o;
        int d = j - i;
        int pg = -1;
        if (d >= 1 && d <= 15) {
            pg = c_off[d - 1] + i;
        } else if (d >= 17 && d <= 31 && ((d - 17) & 1) == 0 && (i & 1) == 0) {
            pg = c_off[15 + ((d - 17) >> 1)] + (i >> 1);
        } else if (d >= 35 && d <= 63 && ((d - 35) & 3) == 0 && (i & 3) == 0) {
            pg = c_off[23 + ((d - 35) >> 2)] + (i >> 2);
        }
        lut[j] = pg;
    }
    __syncthreads();

    float vb = __ldg(vis_b + o);
    float p1 = P[((size_t)b * NG + i) * 768 + o];
    float p2x = P[((size_t)b * NG + i) * 768 + 256 + o];
    const float* P3b = P + (size_t)b * NG * 768 + 512 + o;
    const float* Pcb = Pc + (size_t)b * PPAD * 256 + o;

    float accr[64];
#pragma unroll
    for (int j = 0; j < 64; j++) {
        float v = vb;
        if (j == i) {
            v += p1 + p2x + P3b[(size_t)j * 768];
        } else {
            int pg = lut[j];
            if (pg >= 0) v += p1 + Pcb[(size_t)pg * 256] + P3b[(size_t)j * 768];
        }
        accr[j] = v;
    }

    float4* op = (float4*)(out + (((size_t)b * DCH + o) * NG + i) * NG);
#pragma unroll
    for (int q = 0; q < 16; q++)
        op[q] = make_float4(accr[4 * q], accr[4 * q + 1], accr[4 * q + 2], accr[4 * q + 3]);
}

// ---------------- host ----------------
extern "C" void kernel_launch(void* const* d_in, const int* in_sizes, int n_in,
                              void* d_out, int out_size) {
    const float* x  = (const float*)d_in[0];
    const float* w2 = (const float*)d_in[1];
    const float* b2 = (const float*)d_in[2];
    const float* w3 = (const float*)d_in[3];
    const float* b3 = (const float*)d_in[4];
    const float* vw = (const float*)d_in[5];
    const float* vb = (const float*)d_in[6];
    float* out = (float*)d_out;

    float *Pc, *P;
    uint4 *aH, *aL, *xH, *xL, *wH, *wL, *wbhi, *wblo;
    cudaGetSymbolAddress((void**)&Pc, g_Pc);
    cudaGetSymbolAddress((void**)&P, g_P);
    cudaGetSymbolAddress((void**)&aH, g_act_hi);
    cudaGetSymbolAddress((void**)&aL, g_act_lo);
    cudaGetSymbolAddress((void**)&xH, g_xa_hi);
    cudaGetSymbolAddress((void**)&xL, g_xa_lo);
    cudaGetSymbolAddress((void**)&wH, g_w_hi);
    cudaGetSymbolAddress((void**)&wL, g_w_lo);
    cudaGetSymbolAddress((void**)&wbhi, g_wB_hi);
    cudaGetSymbolAddress((void**)&wblo, g_wB_lo);

    cudaFuncSetAttribute(chain_mma, cudaFuncAttributeMaxDynamicSharedMemorySize,
                         CH_SMEM);
    cudaFuncSetAttribute(gemm_mma, cudaFuncAttributeMaxDynamicSharedMemorySize,
                         PC_SMEM);

    dim3 tb(32, 8);
    split_B<<<768, 256>>>(vw, (__nv_bfloat16*)wbhi, (__nv_bfloat16*)wblo);
    wsplit<<<2048, 512>>>(w2, w3, (__nv_bfloat16*)wH, (__nv_bfloat16*)wL);
    xsplit<<<dim3(2, 8, BATCH), tb>>>(x, (__nv_bfloat16*)xH, (__nv_bfloat16*)xL);

    // tensor-core chain: 32 clusters x 4 CTAs
    chain_mma<<<128, 256, CH_SMEM>>>(xH, xL, wH, wL, b2, b3,
                                     (__nv_bfloat16*)aH, (__nv_bfloat16*)aL);

    // merged x projections on tensor cores: P [B][64][768]
    gemm_mma<<<dim3(1, 12, BATCH), 128, PC_SMEM>>>(xH, xL, wbhi, wblo, P, 64, 768);

    // Pc on tensor cores: uses vis_w slice 1 (rows 256..511 of split B)
    gemm_mma<<<dim3(PPAD / 64, 4, BATCH), 128, PC_SMEM>>>(
        aH, aL, wbhi + 256 * 32, wblo + 256 * 32, Pc, PPAD, 256);

    final_out<<<dim3(NG, BATCH), 256>>>(P, Pc, vb, out);
}

// round 13
// speedup vs baseline: 1.7185x; 1.0010x over previous
#include <cuda_runtime.h>
#include <cuda_bf16.h>
#include <cstdint>
#include <cstddef>

#define BATCH 32
#define DCH 256
#define NG 64
#define PPAD 1088   // padded total conv positions (17 * 64)

__constant__ int c_off[31] = {0,64,128,192,252,312,372,432,488,544,600,656,708,760,812,
                              864,888,912,936,960,980,1000,1020,
                              1040,1048,1056,1064,1072,1076,1080,1084};
__constant__ int c_tb[31]  = {0,2,4,6,8,10,12,14,16,18,20,22,24,26,28, 30,
                              33,35,37,39,41,43,45, 47, 50,52,54,56,58,60,62};
__constant__ int c_taps[31] = {2,2,2,2,2,2,2,2,2,2,2,2,2,2,2, 3, 2,2,2,2,2,2,2, 3,
                               2,2,2,2,2,2,2};
__constant__ int c_cs[31]   = {1,1,1,1,1,1,1,1,1,1,1,1,1,1,1, 2, 1,1,1,1,1,1,1, 2,
                               1,1,1,1,1,1,1};
__constant__ int c_M[31]    = {63,62,61,60,59,58,57,56,55,54,53,52,51,50,49, 24,
                               23,22,21,20,19,18,17, 8, 7,6,5,4,3,2,1};
__constant__ int c_bi[31]   = {0,1,2,3,4,5,6,7,8,9,10,11,12,13,14, 0,
                               15,16,17,18,19,20,21, 1, 22,23,24,25,26,27,28};
__constant__ int c_isk3[31] = {0,0,0,0,0,0,0,0,0,0,0,0,0,0,0, 1, 0,0,0,0,0,0,0, 1,
                               0,0,0,0,0,0,0};
__constant__ int c_tb2[29]  = {0,2,4,6,8,10,12,14,16,18,20,22,24,26,28,
                               33,35,37,39,41,43,45, 50,52,54,56,58,60,62};

// ---------------- scratch ----------------
__device__ float g_Pc[(size_t)BATCH * PPAD * DCH];
__device__ float g_P[(size_t)BATCH * NG * 768];
__device__ uint4 g_act_hi[(size_t)BATCH * PPAD * 256 / 8];
__device__ uint4 g_act_lo[(size_t)BATCH * PPAD * 256 / 8];
__device__ uint4 g_xa_hi[(size_t)BATCH * 64 * 256 / 8];
__device__ uint4 g_xa_lo[(size_t)BATCH * 64 * 256 / 8];
__device__ uint4 g_w_hi[64 * 256 * 256 / 8];
__device__ uint4 g_w_lo[64 * 256 * 256 / 8];
__device__ uint4 g_wB_hi[768 * 256 / 8];
__device__ uint4 g_wB_lo[768 * 256 / 8];

// ---------------- helpers ----------------
__device__ __forceinline__ void cluster_sync_all() {
    asm volatile("barrier.cluster.arrive.aligned;" ::: "memory");
    asm volatile("barrier.cluster.wait.aligned;" ::: "memory");
}
__device__ __forceinline__ uint32_t smem_u32(const void* p) {
    uint32_t a;
    asm("{ .reg .u64 t; cvta.to.shared.u64 t, %1; cvt.u32.u64 %0, t; }"
        : "=r"(a) : "l"(p));
    return a;
}
__device__ __forceinline__ void mma_bf16(float* d, const uint32_t* a,
                                         const uint32_t* b) {
    asm volatile(
        "mma.sync.aligned.m16n8k16.row.col.f32.bf16.bf16.f32 "
        "{%0,%1,%2,%3}, {%4,%5,%6,%7}, {%8,%9}, {%0,%1,%2,%3};"
        : "+f"(d[0]), "+f"(d[1]), "+f"(d[2]), "+f"(d[3])
        : "r"(a[0]), "r"(a[1]), "r"(a[2]), "r"(a[3]), "r"(b[0]), "r"(b[1]));
}
__device__ __forceinline__ void ldsm_x4(uint32_t& r0, uint32_t& r1, uint32_t& r2,
                                        uint32_t& r3, uint32_t a) {
    asm volatile("ldmatrix.sync.aligned.m8n8.x4.shared.b16 {%0,%1,%2,%3}, [%4];"
                 : "=r"(r0), "=r"(r1), "=r"(r2), "=r"(r3) : "r"(a));
}
__device__ __forceinline__ void cp16(uint32_t s, const void* g) {
    asm volatile("cp.async.cg.shared.global [%0], [%1], 16;" :: "r"(s), "l"(g)
                 : "memory");
}
#define CP_COMMIT() asm volatile("cp.async.commit_group;" ::: "memory")
#define CP_WAIT0() asm volatile("cp.async.wait_group 0;" ::: "memory")
#define CP_WAIT1() asm volatile("cp.async.wait_group 1;" ::: "memory")

// ---------------- x -> xact split ----------------
__global__ void xsplit(const float* __restrict__ x,
                       __nv_bfloat16* __restrict__ hi,
                       __nv_bfloat16* __restrict__ lo) {
    __shared__ float t[32][33];
    int b = blockIdx.z;
    int p0 = blockIdx.x * 32, ch0 = blockIdx.y * 32;
    int tx = threadIdx.x, ty = threadIdx.y;
#pragma unroll
    for (int s = 0; s < 32; s += 8) {
        int c = ch0 + ty + s;
        t[ty + s][tx] = x[((size_t)b * DCH + c) * NG + p0 + tx];
    }
    __syncthreads();
#pragma unroll
    for (int s = 0; s < 32; s += 8) {
        int p = p0 + ty + s, c = ch0 + tx;
        float v = t[tx][ty + s];
        __nv_bfloat16 h = __float2bfloat16(v);
        __nv_bfloat16 l = __float2bfloat16(v - __bfloat162float(h));
        size_t o = ((size_t)b * NG + p) * 256 + c;
        hi[o] = h;
        lo[o] = l;
    }
}

// ---------------- weight split ----------------
#define W2TOT (29 * 256 * 256 * 2)
#define WTOT (W2TOT + 2 * 256 * 256 * 3)
__global__ void wsplit(const float* __restrict__ w2, const float* __restrict__ w3,
                       __nv_bfloat16* __restrict__ hi,
                       __nv_bfloat16* __restrict__ lo) {
    for (int idx = blockIdx.x * blockDim.x + threadIdx.x; idx < WTOT;
         idx += gridDim.x * blockDim.x) {
        float v;
        int tap, n, c;
        if (idx < W2TOT) {
            int i2 = idx >> 17;
            int r = idx & 0x1FFFF;
            n = r >> 9;
            int r2 = r & 511;
            c = r2 >> 1;
            int kk = r2 & 1;
            v = w2[idx];
            tap = c_tb2[i2] + kk;
        } else {
            int j = idx - W2TOT;
            int i3 = j / 196608;
            int r = j % 196608;
            n = r / 768;
            int r2 = r % 768;
            c = r2 / 3;
            int kk = r2 % 3;
            v = w3[j];
            tap = (i3 ? 47 : 30) + kk;
        }
        size_t dst = (size_t)tap * 65536 + (size_t)n * 256 + c;
        __nv_bfloat16 h = __float2bfloat16(v);
        __nv_bfloat16 l = __float2bfloat16(v - __bfloat162float(h));
        hi[dst] = h;
        lo[dst] = l;
    }
}

// split full vis_w: row r = s*256+o  ->  B[r][c] = vw[o][s*256+c]
__global__ void split_B(const float* __restrict__ vw,
                        __nv_bfloat16* __restrict__ hi,
                        __nv_bfloat16* __restrict__ lo) {
    int r = blockIdx.x, c = threadIdx.x;
    int o = r & 255, s = r >> 8;
    float v = vw[(size_t)o * 768 + s * 256 + c];
    __nv_bfloat16 h = __float2bfloat16(v);
    __nv_bfloat16 l = __float2bfloat16(v - __bfloat162float(h));
    hi[(size_t)r * 256 + c] = h;
    lo[(size_t)r * 256 + c] = l;
}

// ---------------- fused chain: 512 threads, 2-way K split over warps ----------------
#define CROWB 528
#define CBUF (64 * CROWB)       // 33792 bytes
#define CH_SMEM (6 * CBUF)      // AH | AL | BH0 | BL0 | BH1 | BL1

__global__ void __launch_bounds__(512, 1) __cluster_dims__(4, 1, 1)
chain_mma(const uint4* __restrict__ xaH, const uint4* __restrict__ xaL,
          const uint4* __restrict__ gwH, const uint4* __restrict__ gwL,
          const float* __restrict__ b2, const float* __restrict__ b3,
          __nv_bfloat16* __restrict__ actH, __nv_bfloat16* __restrict__ actL) {
    extern __shared__ char sm[];
    uint32_t sb = smem_u32(sm);
    const uint32_t AHs = sb, ALs = sb + CBUF;
    const uint32_t BH0 = sb + 2 * CBUF, BL0 = sb + 3 * CBUF;
    const uint32_t BH1 = sb + 4 * CBUF, BL1 = sb + 5 * CBUF;
    float* Red = (float*)(sm + 2 * CBUF);  // aliased with BH0 (used between syncs)

    int tid = threadIdx.x;
    int warp = tid >> 5, lane = tid & 31;
    int g = lane >> 2, t = lane & 3;
    int ridx = lane & 15, half = lane >> 4;
    int wm = (warp & 3) * 16;
    int wn = ((warp >> 2) & 1) * 32;
    int kh = warp >> 3;                 // k-half 0/1
    int b = blockIdx.x >> 2;
    int nblk = (blockIdx.x & 3) * 64;
    int lr = tid >> 5;                  // 0..15
    int lq = tid & 31;

    const uint4* act4H = (const uint4*)actH;
    const uint4* act4L = (const uint4*)actL;

    uint32_t roff0 = (wn + ridx) * CROWB + half * 16;
    uint32_t roff1 = (wn + 16 + ridx) * CROWB + half * 16;
    uint32_t obase = (uint32_t)kh * 256;   // kh*8 k-steps * 32B

    auto load_B = [&](int tap, uint32_t BHb, uint32_t BLb) {
        size_t wb = (size_t)tap * 8192 + (size_t)nblk * 32;
#pragma unroll
        for (int i = 0; i < 4; i++) {
            int r = lr + 16 * i;
            uint32_t dst = r * CROWB + lq * 16;
            cp16(BHb + dst, &gwH[wb + (size_t)r * 32 + lq]);
            cp16(BLb + dst, &gwL[wb + (size_t)r * 32 + lq]);
        }
    };

    load_B(0, BH0, BL0);
    load_B(1, BH1, BL1);
    CP_COMMIT();

#pragma unroll 1
    for (int l = 0; l < 31; l++) {
        int taps = c_taps[l], cs = c_cs[l], tb = c_tb[l], M = c_M[l];
        int in_off = (l == 0) ? 0 : c_off[l - 1];
        int out_off = c_off[l];
        const float* bias = c_isk3[l] ? (b3 + c_bi[l] * 256) : (b2 + c_bi[l] * 256);

        if (l == 0) {
            size_t base = (size_t)b * 64 * 32;
#pragma unroll
            for (int i = 0; i < 4; i++) {
                int r = lr + 16 * i;
                uint32_t dst = r * CROWB + lq * 16;
                cp16(AHs + dst, &xaH[base + (size_t)r * 32 + lq]);
                cp16(ALs + dst, &xaL[base + (size_t)r * 32 + lq]);
            }
        } else {
#pragma unroll
            for (int i = 0; i < 4; i++) {
                int r = lr + 16 * i;
                int rr = in_off + r;
                if (rr > PPAD - 1) rr = PPAD - 1;
                size_t src = ((size_t)b * PPAD + rr) * 32 + lq;
                uint32_t dst = r * CROWB + lq * 16;
                cp16(AHs + dst, &act4H[src]);
                cp16(ALs + dst, &act4L[src]);
            }
        }
        CP_COMMIT();

        float acc[4][4];
#pragma unroll
        for (int ni = 0; ni < 4; ni++)
#pragma unroll
            for (int p = 0; p < 4; p++) acc[ni][p] = 0.f;

        bool active = (wm < M);

        auto mma_tap = [&](int tap, uint32_t BHb, uint32_t BLb) {
            int arow = ((wm + ridx) * cs + tap) & 63;
            uint32_t aHb = AHs + arow * CROWB + half * 16 + obase;
            uint32_t aLb = ALs + arow * CROWB + half * 16 + obase;
            uint32_t bh0 = BHb + roff0 + obase, bh1 = BHb + roff1 + obase;
            uint32_t bl0 = BLb + roff0 + obase, bl1 = BLb + roff1 + obase;
#pragma unroll
            for (int ks = 0; ks < 8; ks++) {
                uint32_t o = ks * 32;
                uint32_t ah[4], al[4];
                ldsm_x4(ah[0], ah[1], ah[2], ah[3], aHb + o);
                ldsm_x4(al[0], al[1], al[2], al[3], aLb + o);
                uint32_t p0, p1, p2, p3, q0, q1, q2, q3;
                ldsm_x4(p0, p1, p2, p3, bh0 + o);
                ldsm_x4(q0, q1, q2, q3, bh1 + o);
                uint32_t r0, r1, r2, r3, s0, s1, s2, s3;
                ldsm_x4(r0, r1, r2, r3, bl0 + o);
                ldsm_x4(s0, s1, s2, s3, bl1 + o);
                uint32_t fh0[2] = {p0, p2}, fh1[2] = {p1, p3};
                uint32_t fh2[2] = {q0, q2}, fh3[2] = {q1, q3};
                uint32_t fl0[2] = {r0, r2}, fl1[2] = {r1, r3};
                uint32_t fl2[2] = {s0, s2}, fl3[2] = {s1, s3};
                mma_bf16(acc[0], ah, fh0);
                mma_bf16(acc[1], ah, fh1);
                mma_bf16(acc[2], ah, fh2);
                mma_bf16(acc[3], ah, fh3);
                mma_bf16(acc[0], al, fh0);
                mma_bf16(acc[1], al, fh1);
                mma_bf16(acc[2], al, fh2);
                mma_bf16(acc[3], al, fh3);
                mma_bf16(acc[0], ah, fl0);
                mma_bf16(acc[1], ah, fl1);
                mma_bf16(acc[2], ah, fl2);
                mma_bf16(acc[3], ah, fl3);
            }
        };

        CP_WAIT0();
        __syncthreads();
        if (active) mma_tap(0, BH0, BL0);

        if (taps == 3) {
            __syncthreads();
            load_B(tb + 2, BH0, BL0);
            CP_COMMIT();
            if (active) mma_tap(1, BH1, BL1);
            CP_WAIT0();
            __syncthreads();
            if (active) mma_tap(2, BH0, BL0);
        } else {
            if (active) mma_tap(1, BH1, BL1);
        }

        // ---- K reduction across warp halves (Red aliases BH0) ----
        __syncthreads();
        if (kh == 1 && active) {
            float* rp = Red + ((size_t)(warp & 7) * 32 + lane) * 16;
#pragma unroll
            for (int ni = 0; ni < 4; ni++)
#pragma unroll
                for (int p = 0; p < 4; p++) rp[ni * 4 + p] = acc[ni][p];
        }
        __syncthreads();
        if (kh == 0 && active) {
            const float* rp = Red + ((size_t)warp * 32 + lane) * 16;
#pragma unroll
            for (int ni = 0; ni < 4; ni++)
#pragma unroll
                for (int p = 0; p < 4; p++) acc[ni][p] += rp[ni * 4 + p];
        }
        __syncthreads();

        if (l < 30) {
            load_B(c_tb[l + 1], BH0, BL0);
            load_B(c_tb[l + 1] + 1, BH1, BL1);
            CP_COMMIT();
        }

        // epilogue: kh=0 warps only
        if (kh == 0) {
            int m0g = wm + g;
#pragma unroll
            for (int ni = 0; ni < 4; ni++) {
                int n = nblk + wn + ni * 8 + 2 * t;
                float bv0 = __ldg(bias + n);
                float bv1 = __ldg(bias + n + 1);
                if (m0g < M) {
                    float v0 = acc[ni][0] + bv0, v1 = acc[ni][1] + bv1;
                    size_t o = ((size_t)b * PPAD + out_off + m0g) * 256 + n;
                    __nv_bfloat162 hh, ll;
                    hh.x = __float2bfloat16(v0);
                    hh.y = __float2bfloat16(v1);
                    ll.x = __float2bfloat16(v0 - __bfloat162float(hh.x));
                    ll.y = __float2bfloat16(v1 - __bfloat162float(hh.y));
                    *(__nv_bfloat162*)(actH + o) = hh;
                    *(__nv_bfloat162*)(actL + o) = ll;
                }
                if (m0g + 8 < M) {
                    float v0 = acc[ni][2] + bv0, v1 = acc[ni][3] + bv1;
                    size_t o = ((size_t)b * PPAD + out_off + m0g + 8) * 256 + n;
                    __nv_bfloat162 hh, ll;
                    hh.x = __float2bfloat16(v0);
                    hh.y = __float2bfloat16(v1);
                    ll.x = __float2bfloat16(v0 - __bfloat162float(hh.x));
                    ll.y = __float2bfloat16(v1 - __bfloat162float(hh.y));
                    *(__nv_bfloat162*)(actH + o) = hh;
                    *(__nv_bfloat162*)(actL + o) = ll;
                }
            }
        }
        cluster_sync_all();
    }
}

// ---------------- generic one-tile GEMM (for the x projection) ----------------
#define ROWB 528
#define ABUF (64 * ROWB)
#define SM_AH 0
#define SM_AL ABUF
#define SM_BH (2 * ABUF)
#define SM_BL (3 * ABUF)
#define P_SMEM (4 * ABUF)

__global__ void __launch_bounds__(128, 1)
gemm_mma(const uint4* __restrict__ Ahi, const uint4* __restrict__ Alo,
         const uint4* __restrict__ Bhi, const uint4* __restrict__ Blo,
         float* __restrict__ out, int a_rows, int out_ld) {
    extern __shared__ char sm[];
    int tid = threadIdx.x;
    int warp = tid >> 5, lane = tid & 31;
    int b = blockIdx.z, mt = blockIdx.x, nb = blockIdx.y * 64;

    {
        size_t srcb = ((size_t)b * a_rows + mt * 64) * 32;
#pragma unroll
        for (int i = 0; i < 16; i++) {
            int e = tid + 128 * i;
            int r = e >> 5, q = e & 31;
            int dst = r * ROWB + q * 16;
            *(uint4*)(sm + SM_AH + dst) = Ahi[srcb + (size_t)r * 32 + q];
            *(uint4*)(sm + SM_AL + dst) = Alo[srcb + (size_t)r * 32 + q];
        }
#pragma unroll
        for (int i = 0; i < 16; i++) {
            int e = tid + 128 * i;
            int r = e >> 5, q = e & 31;
            int dst = r * ROWB + q * 16;
            *(uint4*)(sm + SM_BH + dst) = Bhi[(size_t)(nb + r) * 32 + q];
            *(uint4*)(sm + SM_BL + dst) = Blo[(size_t)(nb + r) * 32 + q];
        }
    }
    __syncthreads();

    int g = lane >> 2, t = lane & 3;
    int ridx = lane & 15, half = lane >> 4;
    int wm = (warp >> 1) * 32;
    int wn = (warp & 1) * 32;
    uint32_t sbu = smem_u32(sm);

    uint32_t aoff0 = (wm + ridx) * ROWB + half * 16;
    uint32_t aoff1 = (wm + 16 + ridx) * ROWB + half * 16;
    uint32_t boff0 = (wn + ridx) * ROWB + half * 16;
    uint32_t boff1 = (wn + 16 + ridx) * ROWB + half * 16;

    float acc[2][4][4];
#pragma unroll
    for (int mi = 0; mi < 2; mi++)
#pragma unroll
        for (int ni = 0; ni < 4; ni++)
#pragma unroll
            for (int p = 0; p < 4; p++) acc[mi][ni][p] = 0.f;

#pragma unroll 1
    for (int pass = 0; pass < 3; pass++) {
        uint32_t Ab = sbu + ((pass == 2) ? SM_AL : SM_AH);
        uint32_t Bb = sbu + ((pass == 1) ? SM_BL : SM_BH);
#pragma unroll
        for (int ks = 0; ks < 16; ks++) {
            uint32_t o = ks * 32;
            uint32_t a0[4], a1[4];
            ldsm_x4(a0[0], a0[1], a0[2], a0[3], Ab + aoff0 + o);
            ldsm_x4(a1[0], a1[1], a1[2], a1[3], Ab + aoff1 + o);
            uint32_t p0, p1, p2, p3, q0, q1, q2, q3;
            ldsm_x4(p0, p1, p2, p3, Bb + boff0 + o);
            ldsm_x4(q0, q1, q2, q3, Bb + boff1 + o);
            uint32_t f0[2] = {p0, p2}, f1[2] = {p1, p3};
            uint32_t f2[2] = {q0, q2}, f3[2] = {q1, q3};
            mma_bf16(acc[0][0], a0, f0);
            mma_bf16(acc[0][1], a0, f1);
            mma_bf16(acc[0][2], a0, f2);
            mma_bf16(acc[0][3], a0, f3);
            mma_bf16(acc[1][0], a1, f0);
            mma_bf16(acc[1][1], a1, f1);
            mma_bf16(acc[1][2], a1, f2);
            mma_bf16(acc[1][3], a1, f3);
        }
    }

#pragma unroll
    for (int mi = 0; mi < 2; mi++) {
        int m = mt * 64 + wm + mi * 16 + g;
#pragma unroll
        for (int ni = 0; ni < 4; ni++) {
            int n = nb + wn + ni * 8 + 2 * t;
            float* p0 = out + ((size_t)b * a_rows + m) * out_ld + n;
            float* p1 = out + ((size_t)b * a_rows + m + 8) * out_ld + n;
            *(float2*)p0 = make_float2(acc[mi][ni][0], acc[mi][ni][1]);
            *(float2*)p1 = make_float2(acc[mi][ni][2], acc[mi][ni][3]);
        }
    }
}

// ---------------- Pc GEMM: A-resident, loop over 4 N-tiles, cp.async pipeline ----
#define PCW_SMEM (6 * ABUF)

__global__ void __launch_bounds__(128, 1)
pc_mma(const uint4* __restrict__ Ahi, const uint4* __restrict__ Alo,
       const uint4* __restrict__ Bhi, const uint4* __restrict__ Blo,
       float* __restrict__ Pc) {
    extern __shared__ char sm[];
    uint32_t sb = smem_u32(sm);
    const uint32_t A_H = sb, A_L = sb + ABUF;
    const uint32_t BH[2] = {sb + 2 * ABUF, sb + 4 * ABUF};
    const uint32_t BL[2] = {sb + 3 * ABUF, sb + 5 * ABUF};

    int tid = threadIdx.x;
    int warp = tid >> 5, lane = tid & 31;
    int b = blockIdx.z, mt = blockIdx.x;

    auto loadB = [&](int nt, int buf) {
#pragma unroll
        for (int i = 0; i < 16; i++) {
            int e = tid + 128 * i;
            int r = e >> 5, q = e & 31;
            uint32_t dst = r * ROWB + q * 16;
            cp16(BH[buf] + dst, &Bhi[(size_t)(nt * 64 + r) * 32 + q]);
            cp16(BL[buf] + dst, &Blo[(size_t)(nt * 64 + r) * 32 + q]);
        }
    };

    {
        size_t srcb = ((size_t)b * PPAD + mt * 64) * 32;
#pragma unroll
        for (int i = 0; i < 16; i++) {
            int e = tid + 128 * i;
            int r = e >> 5, q = e & 31;
            uint32_t dst = r * ROWB + q * 16;
            cp16(A_H + dst, &Ahi[srcb + (size_t)r * 32 + q]);
            cp16(A_L + dst, &Alo[srcb + (size_t)r * 32 + q]);
        }
    }
    loadB(0, 0);
    CP_COMMIT();
    loadB(1, 1);
    CP_COMMIT();

    int g = lane >> 2, t = lane & 3;
    int ridx = lane & 15, half = lane >> 4;
    int wm = (warp >> 1) * 32;
    int wn = (warp & 1) * 32;

    uint32_t aoff0 = (wm + ridx) * ROWB + half * 16;
    uint32_t aoff1 = (wm + 16 + ridx) * ROWB + half * 16;
    uint32_t boff0 = (wn + ridx) * ROWB + half * 16;
    uint32_t boff1 = (wn + 16 + ridx) * ROWB + half * 16;

#pragma unroll 1
    for (int nt = 0; nt < 4; nt++) {
        if (nt < 3) CP_WAIT1();
        else CP_WAIT0();
        __syncthreads();

        int buf = nt & 1;
        float acc[2][4][4];
#pragma unroll
        for (int mi = 0; mi < 2; mi++)
#pragma unroll
            for (int ni = 0; ni < 4; ni++)
#pragma unroll
                for (int p = 0; p < 4; p++) acc[mi][ni][p] = 0.f;

#pragma unroll 1
        for (int pass = 0; pass < 3; pass++) {
            uint32_t Ab = (pass == 2) ? A_L : A_H;
            uint32_t Bb = (pass == 1) ? BL[buf] : BH[buf];
#pragma unroll
            for (int ks = 0; ks < 16; ks++) {
                uint32_t o = ks * 32;
                uint32_t a0[4], a1[4];
                ldsm_x4(a0[0], a0[1], a0[2], a0[3], Ab + aoff0 + o);
                ldsm_x4(a1[0], a1[1], a1[2], a1[3], Ab + aoff1 + o);
                uint32_t p0, p1, p2, p3, q0, q1, q2, q3;
                ldsm_x4(p0, p1, p2, p3, Bb + boff0 + o);
                ldsm_x4(q0, q1, q2, q3, Bb + boff1 + o);
                uint32_t f0[2] = {p0, p2}, f1[2] = {p1, p3};
                uint32_t f2[2] = {q0, q2}, f3[2] = {q1, q3};
                mma_bf16(acc[0][0], a0, f0);
                mma_bf16(acc[0][1], a0, f1);
                mma_bf16(acc[0][2], a0, f2);
                mma_bf16(acc[0][3], a0, f3);
                mma_bf16(acc[1][0], a1, f0);
                mma_bf16(acc[1][1], a1, f1);
                mma_bf16(acc[1][2], a1, f2);
                mma_bf16(acc[1][3], a1, f3);
            }
        }
        __syncthreads();
        if (nt + 2 < 4) {
            loadB(nt + 2, buf);
            CP_COMMIT();
        }

        int nb = nt * 64;
#pragma unroll
        for (int mi = 0; mi < 2; mi++) {
            int m = mt * 64 + wm + mi * 16 + g;
#pragma unroll
            for (int ni = 0; ni < 4; ni++) {
                int n = nb + wn + ni * 8 + 2 * t;
                float* p0 = Pc + ((size_t)b * PPAD + m) * 256 + n;
                float* p1 = Pc + ((size_t)b * PPAD + m + 8) * 256 + n;
                *(float2*)p0 = make_float2(acc[mi][ni][0], acc[mi][ni][1]);
                *(float2*)p1 = make_float2(acc[mi][ni][2], acc[mi][ni][3]);
            }
        }
    }
}

// ---------------- final output assembly ----------------
__global__ void __launch_bounds__(256) final_out(
    const float* __restrict__ P, const float* __restrict__ Pc,
    const float* __restrict__ vis_b, float* __restrict__ out) {
    int i = blockIdx.x;
    int b = blockIdx.y;
    int o = threadIdx.x;

    __shared__ int lut[64];
    if (o < 64) {
        int j = o;
        int d = j - i;
        int pg = -1;
        if (d >= 1 && d <= 15) {
            pg = c_off[d - 1] + i;
        } else if (d >= 17 && d <= 31 && ((d - 17) & 1) == 0 && (i & 1) == 0) {
            pg = c_off[15 + ((d - 17) >> 1)] + (i >> 1);
        } else if (d >= 35 && d <= 63 && ((d - 35) & 3) == 0 && (i & 3) == 0) {
            pg = c_off[23 + ((d - 35) >> 2)] + (i >> 2);
        }
        lut[j] = pg;
    }
    __syncthreads();

    float vb = __ldg(vis_b + o);
    float p1 = P[((size_t)b * NG + i) * 768 + o];
    float p2x = P[((size_t)b * NG + i) * 768 + 256 + o];
    const float* P3b = P + (size_t)b * NG * 768 + 512 + o;
    const float* Pcb = Pc + (size_t)b * PPAD * 256 + o;

    float accr[64];
#pragma unroll
    for (int j = 0; j < 64; j++) {
        float v = vb;
        if (j == i) {
            v += p1 + p2x + P3b[(size_t)j * 768];
        } else {
            int pg = lut[j];
            if (pg >= 0) v += p1 + Pcb[(size_t)pg * 256] + P3b[(size_t)j * 768];
        }
        accr[j] = v;
    }

    float4* op = (float4*)(out + (((size_t)b * DCH + o) * NG + i) * NG);
#pragma unroll
    for (int q = 0; q < 16; q++)
        op[q] = make_float4(accr[4 * q], accr[4 * q + 1], accr[4 * q + 2], accr[4 * q + 3]);
}

// ---------------- host ----------------
extern "C" void kernel_launch(void* const* d_in, const int* in_sizes, int n_in,
                              void* d_out, int out_size) {
    const float* x  = (const float*)d_in[0];
    const float* w2 = (const float*)d_in[1];
    const float* b2 = (const float*)d_in[2];
    const float* w3 = (const float*)d_in[3];
    const float* b3 = (const float*)d_in[4];
    const float* vw = (const float*)d_in[5];
    const float* vb = (const float*)d_in[6];
    float* out = (float*)d_out;

    float *Pc, *P;
    uint4 *aH, *aL, *xH, *xL, *wH, *wL, *wbhi, *wblo;
    cudaGetSymbolAddress((void**)&Pc, g_Pc);
    cudaGetSymbolAddress((void**)&P, g_P);
    cudaGetSymbolAddress((void**)&aH, g_act_hi);
    cudaGetSymbolAddress((void**)&aL, g_act_lo);
    cudaGetSymbolAddress((void**)&xH, g_xa_hi);
    cudaGetSymbolAddress((void**)&xL, g_xa_lo);
    cudaGetSymbolAddress((void**)&wH, g_w_hi);
    cudaGetSymbolAddress((void**)&wL, g_w_lo);
    cudaGetSymbolAddress((void**)&wbhi, g_wB_hi);
    cudaGetSymbolAddress((void**)&wblo, g_wB_lo);

    cudaFuncSetAttribute(chain_mma, cudaFuncAttributeMaxDynamicSharedMemorySize,
                         CH_SMEM);
    cudaFuncSetAttribute(gemm_mma, cudaFuncAttributeMaxDynamicSharedMemorySize,
                         P_SMEM);
    cudaFuncSetAttribute(pc_mma, cudaFuncAttributeMaxDynamicSharedMemorySize,
                         PCW_SMEM);

    dim3 tb(32, 8);
    split_B<<<768, 256>>>(vw, (__nv_bfloat16*)wbhi, (__nv_bfloat16*)wblo);
    wsplit<<<2048, 512>>>(w2, w3, (__nv_bfloat16*)wH, (__nv_bfloat16*)wL);
    xsplit<<<dim3(2, 8, BATCH), tb>>>(x, (__nv_bfloat16*)xH, (__nv_bfloat16*)xL);

    // tensor-core chain: 32 clusters x 4 CTAs, 512 threads (2-way K split)
    chain_mma<<<128, 512, CH_SMEM>>>(xH, xL, wH, wL, b2, b3,
                                     (__nv_bfloat16*)aH, (__nv_bfloat16*)aL);

    // merged x projections on tensor cores: P [B][64][768]
    gemm_mma<<<dim3(1, 12, BATCH), 128, P_SMEM>>>(xH, xL, wbhi, wblo, P, 64, 768);

    // Pc: A-resident, loops over 4 N-tiles (vis_w slice 1 = rows 256..511)
    pc_mma<<<dim3(PPAD / 64, 1, BATCH), 128, PCW_SMEM>>>(
        aH, aL, wbhi + 256 * 32, wblo + 256 * 32, Pc);

    final_out<<<dim3(NG, BATCH), 256>>>(P, Pc, vb, out);
}